// round 12
// baseline (speedup 1.0000x reference)
#include <cuda_runtime.h>
#include <cuda_bf16.h>
#include <cstdint>

#define Dn 1024
#define Bn 16
#define Rn 100

typedef __nv_bfloat16 bf16;
typedef __nv_bfloat162 bf162;

// Scratch (device globals; no allocations allowed).
// ONLY referenced from device code (Round-6 lesson).
__device__ float g_mb[Dn];
__device__ bf16 g_QWh[Dn * Dn], g_QWl[Dn * Dn];
__device__ bf16 g_ETh[Dn * Dn], g_ETl[Dn * Dn];
__device__ bf16 g_Wh[Dn * Dn],  g_Wl[Dn * Dn];
__device__ bf16 g_Mh[Dn * Dn],  g_Ml[Dn * Dn];
__device__ bf16 g_GTh[Dn * Dn], g_GTl[Dn * Dn];
__device__ bf16 g_Ah[Bn * Dn * Dn];
__device__ bf16 g_Al[Bn * Dn * Dn];

__device__ __forceinline__ void split_f32(float v, bf16& h, bf16& l) {
    h = __float2bfloat16_rn(v);
    l = __float2bfloat16_rn(v - __bfloat162float(h));
}

__device__ __forceinline__ void cp_async16(uint32_t dst_smem, const void* src) {
    asm volatile("cp.async.cg.shared.global [%0], [%1], 16;" :: "r"(dst_smem), "l"(src));
}
__device__ __forceinline__ void cp_commit() { asm volatile("cp.async.commit_group;"); }
__device__ __forceinline__ void cp_wait1() { asm volatile("cp.async.wait_group 1;"); }

__device__ __forceinline__ uint32_t smem_u32(const void* p) {
    uint32_t a;
    asm("{ .reg .u64 t; cvta.to.shared.u64 t, %1; cvt.u32.u64 %0, t; }" : "=r"(a) : "l"(p));
    return a;
}

__device__ __forceinline__ void ldsm_x4(uint32_t& r0, uint32_t& r1, uint32_t& r2, uint32_t& r3,
                                        uint32_t addr) {
    asm volatile("ldmatrix.sync.aligned.m8n8.x4.shared.b16 {%0,%1,%2,%3}, [%4];"
                 : "=r"(r0), "=r"(r1), "=r"(r2), "=r"(r3) : "r"(addr));
}

// ---------------------------------------------------------------------------
// Prework kernels (proven)
// ---------------------------------------------------------------------------
__global__ void reduce_w_kernel(const float* __restrict__ gw) {
    int i4 = blockIdx.x * blockDim.x + threadIdx.x;
    const float4* p = reinterpret_cast<const float4*>(gw);
    float ax = 0.f, ay = 0.f, az = 0.f, aw = 0.f;
    #pragma unroll 4
    for (int r = 0; r < Rn; ++r) {
        float4 v = p[(size_t)r * (Dn * Dn / 4) + i4];
        ax += v.x; ay += v.y; az += v.z; aw += v.w;
    }
    const float inv = 1.0f / (float)Rn;
    float vv[4] = {ax * inv, ay * inv, az * inv, aw * inv};
    bf16 h[4], l[4];
    #pragma unroll
    for (int q = 0; q < 4; ++q) split_f32(vv[q], h[q], l[q]);
    reinterpret_cast<bf162*>(g_Wh)[i4 * 2]     = bf162(h[0], h[1]);
    reinterpret_cast<bf162*>(g_Wh)[i4 * 2 + 1] = bf162(h[2], h[3]);
    reinterpret_cast<bf162*>(g_Wl)[i4 * 2]     = bf162(l[0], l[1]);
    reinterpret_cast<bf162*>(g_Wl)[i4 * 2 + 1] = bf162(l[2], l[3]);
}

__global__ void reduce_b_kernel(const float* __restrict__ gb) {
    int k = blockIdx.x * blockDim.x + threadIdx.x;
    float acc = 0.f;
    #pragma unroll 4
    for (int r = 0; r < Rn; ++r) acc += gb[r * Dn + k];
    g_mb[k] = acc / (float)Rn;
}

__global__ void split_QW_kernel(const float* __restrict__ qw) {
    int i4 = blockIdx.x * blockDim.x + threadIdx.x;
    float4 v = reinterpret_cast<const float4*>(qw)[i4];
    float vv[4] = {v.x, v.y, v.z, v.w};
    bf16 h[4], l[4];
    #pragma unroll
    for (int q = 0; q < 4; ++q) split_f32(vv[q], h[q], l[q]);
    reinterpret_cast<bf162*>(g_QWh)[i4 * 2]     = bf162(h[0], h[1]);
    reinterpret_cast<bf162*>(g_QWh)[i4 * 2 + 1] = bf162(h[2], h[3]);
    reinterpret_cast<bf162*>(g_QWl)[i4 * 2]     = bf162(l[0], l[1]);
    reinterpret_cast<bf162*>(g_QWl)[i4 * 2 + 1] = bf162(l[2], l[3]);
}

// A[b,i,m] = cos(ph[i,m]) * x[b,m] -> bf16 hi/lo (cos fused)
__global__ void split_A_kernel(const float* __restrict__ x, const float* __restrict__ ph) {
    int b = blockIdx.y;
    int i4 = blockIdx.x * blockDim.x + threadIdx.x;
    float4 pv = reinterpret_cast<const float4*>(ph)[i4];
    int m = (i4 * 4) & (Dn - 1);
    float4 xv = *reinterpret_cast<const float4*>(x + (size_t)b * Dn + m);
    float vv[4] = {cosf(pv.x) * xv.x, cosf(pv.y) * xv.y,
                   cosf(pv.z) * xv.z, cosf(pv.w) * xv.w};
    bf16 h[4], l[4];
    #pragma unroll
    for (int q = 0; q < 4; ++q) split_f32(vv[q], h[q], l[q]);
    size_t o2 = ((size_t)b << 19) + (size_t)i4 * 2;
    reinterpret_cast<bf162*>(g_Ah)[o2]     = bf162(h[0], h[1]);
    reinterpret_cast<bf162*>(g_Ah)[o2 + 1] = bf162(h[2], h[3]);
    reinterpret_cast<bf162*>(g_Al)[o2]     = bf162(l[0], l[1]);
    reinterpret_cast<bf162*>(g_Al)[o2 + 1] = bf162(l[2], l[3]);
}

__global__ void transpose_split_E_kernel(const float* __restrict__ in) {
    __shared__ float tile[32][33];
    int x = blockIdx.x * 32 + threadIdx.x;
    int y = blockIdx.y * 32 + threadIdx.y;
    #pragma unroll
    for (int j = 0; j < 32; j += 8)
        tile[threadIdx.y + j][threadIdx.x] = in[(y + j) * Dn + x];
    __syncthreads();
    x = blockIdx.y * 32 + threadIdx.x;
    y = blockIdx.x * 32 + threadIdx.y;
    #pragma unroll
    for (int j = 0; j < 32; j += 8) {
        float v = tile[threadIdx.x][threadIdx.y + j];
        bf16 h, l; split_f32(v, h, l);
        g_ETh[(y + j) * Dn + x] = h;
        g_ETl[(y + j) * Dn + x] = l;
    }
}

// ---------------------------------------------------------------------------
// mma.sync bf16 m16n8k16 (row.col)
// ---------------------------------------------------------------------------
__device__ __forceinline__ void mma_bf16(float* c, const uint32_t* a, const uint32_t* b) {
    asm volatile(
        "mma.sync.aligned.m16n8k16.row.col.f32.bf16.bf16.f32 "
        "{%0,%1,%2,%3}, {%4,%5,%6,%7}, {%8,%9}, {%0,%1,%2,%3};"
        : "+f"(c[0]), "+f"(c[1]), "+f"(c[2]), "+f"(c[3])
        : "r"(a[0]), "r"(a[1]), "r"(a[2]), "r"(a[3]), "r"(b[0]), "r"(b[1]));
}

// ---------------------------------------------------------------------------
// Chain split GEMM body (proven): C[i,n] = sum_k A[i,k]*B[n,k]
// ---------------------------------------------------------------------------
template <int WRITE_BF16>
__device__ __forceinline__ void gemm_split_body(
        const bf16* __restrict__ Ah, const bf16* __restrict__ Al,
        const bf16* __restrict__ Bh, const bf16* __restrict__ Bl,
        float* __restrict__ Cf, bf16* __restrict__ Ch, bf16* __restrict__ Cl) {
    constexpr int BM = 128, BK = 32;
    constexpr int PA = BK + 8;
    constexpr int MT = 4, NT = 4;

    __shared__ bf16 sAh[BM * PA];
    __shared__ bf16 sAl[BM * PA];
    __shared__ bf16 sBh[BM * PA];
    __shared__ bf16 sBl[BM * PA];

    const int i0 = blockIdx.y * BM;
    const int n0 = blockIdx.x * BM;

    const int tid  = threadIdx.x;
    const int w    = tid >> 5;
    const int lane = tid & 31;
    const int wm   = w >> 2;
    const int wn   = w & 3;
    const int gid  = lane >> 2;
    const int tig  = lane & 3;

    float acc[MT][NT][4];
    #pragma unroll
    for (int mt = 0; mt < MT; ++mt)
        #pragma unroll
        for (int nt = 0; nt < NT; ++nt)
            #pragma unroll
            for (int q = 0; q < 4; ++q) acc[mt][nt][q] = 0.f;

    for (int k0 = 0; k0 < Dn; k0 += BK) {
        #pragma unroll
        for (int l = 0; l < 2; ++l) {
            int idx = tid + l * 256;
            int row = idx >> 2, c8 = (idx & 3) * 8;
            size_t goA = (size_t)(i0 + row) * Dn + k0 + c8;
            size_t goB = (size_t)(n0 + row) * Dn + k0 + c8;
            int so = row * PA + c8;
            *reinterpret_cast<uint4*>(&sAh[so]) = *reinterpret_cast<const uint4*>(Ah + goA);
            *reinterpret_cast<uint4*>(&sAl[so]) = *reinterpret_cast<const uint4*>(Al + goA);
            *reinterpret_cast<uint4*>(&sBh[so]) = *reinterpret_cast<const uint4*>(Bh + goB);
            *reinterpret_cast<uint4*>(&sBl[so]) = *reinterpret_cast<const uint4*>(Bl + goB);
        }
        __syncthreads();

        #pragma unroll
        for (int ks = 0; ks < BK; ks += 16) {
            uint32_t bh[NT][2], bl[NT][2];
            #pragma unroll
            for (int nt = 0; nt < NT; ++nt) {
                int bn = wn * 32 + nt * 8 + gid;
                int o = bn * PA + ks + tig * 2;
                bh[nt][0] = *reinterpret_cast<const uint32_t*>(&sBh[o]);
                bh[nt][1] = *reinterpret_cast<const uint32_t*>(&sBh[o + 8]);
                bl[nt][0] = *reinterpret_cast<const uint32_t*>(&sBl[o]);
                bl[nt][1] = *reinterpret_cast<const uint32_t*>(&sBl[o + 8]);
            }
            #pragma unroll
            for (int mt = 0; mt < MT; ++mt) {
                int ar = wm * 64 + mt * 16 + gid;
                int o0 = ar * PA + ks + tig * 2, o1 = o0 + 8 * PA;
                uint32_t ah[4], al[4];
                ah[0] = *reinterpret_cast<const uint32_t*>(&sAh[o0]);
                ah[1] = *reinterpret_cast<const uint32_t*>(&sAh[o1]);
                ah[2] = *reinterpret_cast<const uint32_t*>(&sAh[o0 + 8]);
                ah[3] = *reinterpret_cast<const uint32_t*>(&sAh[o1 + 8]);
                al[0] = *reinterpret_cast<const uint32_t*>(&sAl[o0]);
                al[1] = *reinterpret_cast<const uint32_t*>(&sAl[o1]);
                al[2] = *reinterpret_cast<const uint32_t*>(&sAl[o0 + 8]);
                al[3] = *reinterpret_cast<const uint32_t*>(&sAl[o1 + 8]);
                #pragma unroll
                for (int nt = 0; nt < NT; ++nt) {
                    mma_bf16(acc[mt][nt], ah, bh[nt]);
                    mma_bf16(acc[mt][nt], ah, bl[nt]);
                    mma_bf16(acc[mt][nt], al, bh[nt]);
                }
            }
        }
        __syncthreads();
    }

    #pragma unroll
    for (int mt = 0; mt < MT; ++mt) {
        int row = i0 + wm * 64 + mt * 16 + gid;
        #pragma unroll
        for (int nt = 0; nt < NT; ++nt) {
            int col = n0 + wn * 32 + nt * 8 + tig * 2;
            if (WRITE_BF16) {
                bf16 h0, l0, h1, l1;
                split_f32(acc[mt][nt][0], h0, l0);
                split_f32(acc[mt][nt][1], h1, l1);
                *reinterpret_cast<bf162*>(Ch + (size_t)row * Dn + col) = bf162(h0, h1);
                *reinterpret_cast<bf162*>(Cl + (size_t)row * Dn + col) = bf162(l0, l1);
                split_f32(acc[mt][nt][2], h0, l0);
                split_f32(acc[mt][nt][3], h1, l1);
                *reinterpret_cast<bf162*>(Ch + (size_t)(row + 8) * Dn + col) = bf162(h0, h1);
                *reinterpret_cast<bf162*>(Cl + (size_t)(row + 8) * Dn + col) = bf162(l0, l1);
            } else {
                float2 v0 = {acc[mt][nt][0], acc[mt][nt][1]};
                float2 v1 = {acc[mt][nt][2], acc[mt][nt][3]};
                *reinterpret_cast<float2*>(Cf + (size_t)row * Dn + col) = v0;
                *reinterpret_cast<float2*>(Cf + (size_t)(row + 8) * Dn + col) = v1;
            }
        }
    }
}

__global__ void __launch_bounds__(256, 1) gemm_M_kernel() {
    gemm_split_body<1>(g_QWh, g_QWl, g_ETh, g_ETl, nullptr, g_Mh, g_Ml);
}
// G^T directly: C[k,m] = sum_j Wsum[k,j]*M[m,j]
__global__ void __launch_bounds__(256, 1) gemm_GT_kernel() {
    gemm_split_body<1>(g_Wh, g_Wl, g_Mh, g_Ml, nullptr, g_GTh, g_GTl);
}

// ---------------------------------------------------------------------------
// Final GEMM: 128(M) x 64(N) tiles, 2048 CTAs, hard 2 CTAs/SM (smem cap).
// out[b,i,k] = sum_m A[b,i,m] * GT[k,m] + mb[k]
// 8 warps as 4(m) x 2(n), warp tile 32x32 (MT=2, NT=4).
// Dynamic smem: 2 stages x 18432B used; 78336B requested to cap occupancy at 2.
// ---------------------------------------------------------------------------
static constexpr int FIN_SMEM_REQ = 78336;   // > 228KB/3 -> max 2 CTAs/SM
static constexpr int FIN_STAGE    = 18432;   // 128*48 + 128*48 + 64*48 + 64*48 bytes
static constexpr int FIN_AH_OFF   = 0;
static constexpr int FIN_AL_OFF   = 6144;    // 128 rows * 48B
static constexpr int FIN_BH_OFF   = 12288;
static constexpr int FIN_BL_OFF   = 15360;   // + 64 rows * 48B

__global__ void __launch_bounds__(256, 2)
gemm_final_kernel(float* __restrict__ out) {
    constexpr int BK = 16;
    constexpr int PA = 24;           // bf16 elements per row slot (48B pitch)
    constexpr int PAB = 48;          // bytes per row
    constexpr int MT = 2, NT = 4;
    constexpr int NK = Dn / BK;      // 64

    extern __shared__ char dynsm[];
    const uint32_t sb = smem_u32(dynsm);

    const int b  = blockIdx.z;
    const int i0 = blockIdx.y * 128;
    const int n0 = blockIdx.x * 64;
    const bf16* __restrict__ Ahb = g_Ah + ((size_t)b << 20);
    const bf16* __restrict__ Alb = g_Al + ((size_t)b << 20);

    const int tid  = threadIdx.x;
    const int w    = tid >> 5;
    const int lane = tid & 31;
    const int wm   = w >> 1;          // 0..3
    const int wn   = w & 1;           // 0..1
    const int gid  = lane >> 2;
    const int tig  = lane & 3;

    // cp.async copy slots
    const int crowA = tid >> 1;                   // 0..127
    const int cc8   = (tid & 1) * 8;
    const uint32_t csoA = (uint32_t)(crowA * PA + cc8) * 2;
    const bool bload = (tid < 128);
    const int crowB = tid >> 1;                   // 0..63 when bload
    const uint32_t csoB = (uint32_t)(crowB * PA + cc8) * 2;

    uint32_t cpAh[2], cpAl[2], cpBh[2], cpBl[2];
    #pragma unroll
    for (int s = 0; s < 2; ++s) {
        cpAh[s] = sb + s * FIN_STAGE + FIN_AH_OFF + csoA;
        cpAl[s] = sb + s * FIN_STAGE + FIN_AL_OFF + csoA;
        cpBh[s] = sb + s * FIN_STAGE + FIN_BH_OFF + csoB;
        cpBl[s] = sb + s * FIN_STAGE + FIN_BL_OFF + csoB;
    }
    const size_t gA = (size_t)(i0 + crowA) * Dn + cc8;
    const size_t gB = (size_t)(n0 + crowB) * Dn + cc8;

    // ldmatrix per-lane addresses (proven R10 mapping)
    const uint32_t aOff = (uint32_t)((wm * 32 + (lane & 15)) * PAB + (lane >> 4) * 16);
    const uint32_t bOff = (uint32_t)((wn * 32 + (lane & 7) + ((lane >> 4) << 3)) * PAB
                                     + ((lane >> 3) & 1) * 16);
    uint32_t aHa[2], aLa[2], bHa[2], bLa[2];
    #pragma unroll
    for (int s = 0; s < 2; ++s) {
        aHa[s] = sb + s * FIN_STAGE + FIN_AH_OFF + aOff;
        aLa[s] = sb + s * FIN_STAGE + FIN_AL_OFF + aOff;
        bHa[s] = sb + s * FIN_STAGE + FIN_BH_OFF + bOff;
        bLa[s] = sb + s * FIN_STAGE + FIN_BL_OFF + bOff;
    }

    float acc[MT][NT][4];
    #pragma unroll
    for (int mt = 0; mt < MT; ++mt)
        #pragma unroll
        for (int nt = 0; nt < NT; ++nt)
            #pragma unroll
            for (int q = 0; q < 4; ++q) acc[mt][nt][q] = 0.f;

    // prologue: stage 0 <- kt 0
    cp_async16(cpAh[0], Ahb + gA);
    cp_async16(cpAl[0], Alb + gA);
    if (bload) {
        cp_async16(cpBh[0], g_GTh + gB);
        cp_async16(cpBl[0], g_GTl + gB);
    }
    cp_commit();

    for (int kt = 0; kt < NK; ++kt) {
        int st = kt & 1;
        if (kt + 1 < NK) {
            int ko = (kt + 1) * BK;
            int ns = st ^ 1;
            cp_async16(cpAh[ns], Ahb + gA + ko);
            cp_async16(cpAl[ns], Alb + gA + ko);
            if (bload) {
                cp_async16(cpBh[ns], g_GTh + gB + ko);
                cp_async16(cpBl[ns], g_GTl + gB + ko);
            }
        }
        cp_commit();
        cp_wait1();
        __syncthreads();

        // B fragments: 2 ldmatrix.x4 per hi/lo (covers nt pairs)
        uint32_t bh[NT][2], bl[NT][2];
        #pragma unroll
        for (int j = 0; j < 2; ++j) {
            uint32_t r0, r1, r2, r3;
            ldsm_x4(r0, r1, r2, r3, bHa[st] + j * 16 * PAB);
            bh[2 * j][0] = r0; bh[2 * j][1] = r1;
            bh[2 * j + 1][0] = r2; bh[2 * j + 1][1] = r3;
            ldsm_x4(r0, r1, r2, r3, bLa[st] + j * 16 * PAB);
            bl[2 * j][0] = r0; bl[2 * j][1] = r1;
            bl[2 * j + 1][0] = r2; bl[2 * j + 1][1] = r3;
        }
        #pragma unroll
        for (int mt = 0; mt < MT; ++mt) {
            uint32_t ah[4], al[4];
            ldsm_x4(ah[0], ah[1], ah[2], ah[3], aHa[st] + mt * 16 * PAB);
            ldsm_x4(al[0], al[1], al[2], al[3], aLa[st] + mt * 16 * PAB);
            #pragma unroll
            for (int nt = 0; nt < NT; ++nt) {
                mma_bf16(acc[mt][nt], ah, bh[nt]);
                mma_bf16(acc[mt][nt], ah, bl[nt]);
                mma_bf16(acc[mt][nt], al, bh[nt]);
            }
        }
        __syncthreads();
    }

    float* __restrict__ outb = out + (size_t)b * Dn * Dn;
    #pragma unroll
    for (int mt = 0; mt < MT; ++mt) {
        int row = i0 + wm * 32 + mt * 16 + gid;
        #pragma unroll
        for (int nt = 0; nt < NT; ++nt) {
            int col = n0 + wn * 32 + nt * 8 + tig * 2;
            float2 mbv = *reinterpret_cast<const float2*>(&g_mb[col]);
            float2 v0 = {acc[mt][nt][0] + mbv.x, acc[mt][nt][1] + mbv.y};
            float2 v1 = {acc[mt][nt][2] + mbv.x, acc[mt][nt][3] + mbv.y};
            *reinterpret_cast<float2*>(outb + (size_t)row * Dn + col) = v0;
            *reinterpret_cast<float2*>(outb + (size_t)(row + 8) * Dn + col) = v1;
        }
    }
}

// ---------------------------------------------------------------------------
// kernel_launch — dual-stream fork/join (proven R11 pattern).
// ---------------------------------------------------------------------------
extern "C" void kernel_launch(void* const* d_in, const int* in_sizes, int n_in,
                              void* d_out, int out_size) {
    const float* x  = (const float*)d_in[0];
    const float* qw = (const float*)d_in[1];
    const float* ph = (const float*)d_in[2];
    const float* em = (const float*)d_in[3];
    const float* gw = (const float*)d_in[4];
    const float* gb = (const float*)d_in[5];
    float* out = (float*)d_out;

    static cudaStream_t s2 = nullptr;
    static cudaEvent_t eFork = nullptr, eM = nullptr, eJoin = nullptr;
    static bool init_tried = false;
    if (!init_tried) {
        init_tried = true;
        cudaFuncSetAttribute(gemm_final_kernel,
                             cudaFuncAttributeMaxDynamicSharedMemorySize, FIN_SMEM_REQ);
        if (cudaStreamCreateWithFlags(&s2, cudaStreamNonBlocking) != cudaSuccess) s2 = nullptr;
        if (s2) {
            cudaEventCreateWithFlags(&eFork, cudaEventDisableTiming);
            cudaEventCreateWithFlags(&eM,    cudaEventDisableTiming);
            cudaEventCreateWithFlags(&eJoin, cudaEventDisableTiming);
        }
    }

    const dim3 finGrid(Dn / 64, Dn / 128, Bn);   // 16 x 8 x 16 = 2048 CTAs

    if (s2) {
        // fork
        cudaEventRecord(eFork, 0);
        cudaStreamWaitEvent(s2, eFork, 0);
        // branch A (main stream): the 400MB HBM-bound reduction
        reduce_w_kernel<<<(Dn * Dn / 4) / 256, 256>>>(gw);
        // branch B (s2): small-kernel chain
        reduce_b_kernel<<<Dn / 256, 256, 0, s2>>>(gb);
        split_QW_kernel<<<(Dn * Dn / 4) / 256, 256, 0, s2>>>(qw);
        transpose_split_E_kernel<<<dim3(Dn / 32, Dn / 32), dim3(32, 8), 0, s2>>>(em);
        gemm_M_kernel<<<dim3(Dn / 128, Dn / 128), 256, 0, s2>>>();
        cudaEventRecord(eM, s2);
        split_A_kernel<<<dim3((Dn * Dn / 4) / 256, Bn), 256, 0, s2>>>(x, ph);
        cudaEventRecord(eJoin, s2);
        // join: GT needs Wsum (branch A) + M (eM)
        cudaStreamWaitEvent(0, eM, 0);
        gemm_GT_kernel<<<dim3(Dn / 128, Dn / 128), 256>>>();
        cudaStreamWaitEvent(0, eJoin, 0);
        gemm_final_kernel<<<finGrid, 256, FIN_SMEM_REQ>>>(out);
    } else {
        // fallback: single-stream, dependency-correct order
        reduce_b_kernel<<<Dn / 256, 256>>>(gb);
        split_QW_kernel<<<(Dn * Dn / 4) / 256, 256>>>(qw);
        transpose_split_E_kernel<<<dim3(Dn / 32, Dn / 32), dim3(32, 8)>>>(em);
        gemm_M_kernel<<<dim3(Dn / 128, Dn / 128), 256>>>();
        split_A_kernel<<<dim3((Dn * Dn / 4) / 256, Bn), 256>>>(x, ph);
        reduce_w_kernel<<<(Dn * Dn / 4) / 256, 256>>>(gw);
        gemm_GT_kernel<<<dim3(Dn / 128, Dn / 128), 256>>>();
        gemm_final_kernel<<<finGrid, 256, FIN_SMEM_REQ>>>(out);
    }
}

// round 14
// speedup vs baseline: 1.3863x; 1.3863x over previous
#include <cuda_runtime.h>
#include <cuda_bf16.h>
#include <cuda_fp16.h>
#include <cstdint>

#define Dn 1024
#define Bn 16
#define Rn 100

typedef __nv_bfloat16 bf16;
typedef __nv_bfloat162 bf162;

// Scratch (device globals; no allocations allowed).
// ONLY referenced from device code (Round-6 lesson).
__device__ float g_mb[Dn];
__device__ bf16 g_QWh[Dn * Dn], g_QWl[Dn * Dn];
__device__ bf16 g_ETh[Dn * Dn], g_ETl[Dn * Dn];
__device__ bf16 g_Wh[Dn * Dn],  g_Wl[Dn * Dn];
__device__ bf16 g_Mh[Dn * Dn],  g_Ml[Dn * Dn];
__device__ __half g_GTf[Dn * Dn];            // GT single fp16 [k,m]
__device__ __half g_Ahf[Bn * Dn * Dn];       // A fp16 hi [b,i,m]
__device__ __half g_Alf[Bn * Dn * Dn];       // A fp16 lo

__device__ __forceinline__ void split_f32(float v, bf16& h, bf16& l) {
    h = __float2bfloat16_rn(v);
    l = __float2bfloat16_rn(v - __bfloat162float(h));
}
__device__ __forceinline__ void split_f32h(float v, __half& h, __half& l) {
    h = __float2half_rn(v);
    l = __float2half_rn(v - __half2float(h));
}

__device__ __forceinline__ void cp_async16(uint32_t dst_smem, const void* src) {
    asm volatile("cp.async.cg.shared.global [%0], [%1], 16;" :: "r"(dst_smem), "l"(src));
}
__device__ __forceinline__ void cp_commit() { asm volatile("cp.async.commit_group;"); }
__device__ __forceinline__ void cp_wait1() { asm volatile("cp.async.wait_group 1;"); }

__device__ __forceinline__ uint32_t smem_u32(const void* p) {
    uint32_t a;
    asm("{ .reg .u64 t; cvta.to.shared.u64 t, %1; cvt.u32.u64 %0, t; }" : "=r"(a) : "l"(p));
    return a;
}

__device__ __forceinline__ void ldsm_x4(uint32_t& r0, uint32_t& r1, uint32_t& r2, uint32_t& r3,
                                        uint32_t addr) {
    asm volatile("ldmatrix.sync.aligned.m8n8.x4.shared.b16 {%0,%1,%2,%3}, [%4];"
                 : "=r"(r0), "=r"(r1), "=r"(r2), "=r"(r3) : "r"(addr));
}

// ---------------------------------------------------------------------------
// Prework kernels (proven)
// ---------------------------------------------------------------------------
__global__ void reduce_w_kernel(const float* __restrict__ gw) {
    int i4 = blockIdx.x * blockDim.x + threadIdx.x;
    const float4* p = reinterpret_cast<const float4*>(gw);
    float ax = 0.f, ay = 0.f, az = 0.f, aw = 0.f;
    #pragma unroll 4
    for (int r = 0; r < Rn; ++r) {
        float4 v = p[(size_t)r * (Dn * Dn / 4) + i4];
        ax += v.x; ay += v.y; az += v.z; aw += v.w;
    }
    const float inv = 1.0f / (float)Rn;
    float vv[4] = {ax * inv, ay * inv, az * inv, aw * inv};
    bf16 h[4], l[4];
    #pragma unroll
    for (int q = 0; q < 4; ++q) split_f32(vv[q], h[q], l[q]);
    reinterpret_cast<bf162*>(g_Wh)[i4 * 2]     = bf162(h[0], h[1]);
    reinterpret_cast<bf162*>(g_Wh)[i4 * 2 + 1] = bf162(h[2], h[3]);
    reinterpret_cast<bf162*>(g_Wl)[i4 * 2]     = bf162(l[0], l[1]);
    reinterpret_cast<bf162*>(g_Wl)[i4 * 2 + 1] = bf162(l[2], l[3]);
}

__global__ void reduce_b_kernel(const float* __restrict__ gb) {
    int k = blockIdx.x * blockDim.x + threadIdx.x;
    float acc = 0.f;
    #pragma unroll 4
    for (int r = 0; r < Rn; ++r) acc += gb[r * Dn + k];
    g_mb[k] = acc / (float)Rn;
}

__global__ void split_QW_kernel(const float* __restrict__ qw) {
    int i4 = blockIdx.x * blockDim.x + threadIdx.x;
    float4 v = reinterpret_cast<const float4*>(qw)[i4];
    float vv[4] = {v.x, v.y, v.z, v.w};
    bf16 h[4], l[4];
    #pragma unroll
    for (int q = 0; q < 4; ++q) split_f32(vv[q], h[q], l[q]);
    reinterpret_cast<bf162*>(g_QWh)[i4 * 2]     = bf162(h[0], h[1]);
    reinterpret_cast<bf162*>(g_QWh)[i4 * 2 + 1] = bf162(h[2], h[3]);
    reinterpret_cast<bf162*>(g_QWl)[i4 * 2]     = bf162(l[0], l[1]);
    reinterpret_cast<bf162*>(g_QWl)[i4 * 2 + 1] = bf162(l[2], l[3]);
}

// A[b,i,m] = cos(ph[i,m]) * x[b,m] -> fp16 hi/lo (cos fused)
__global__ void split_A_kernel(const float* __restrict__ x, const float* __restrict__ ph) {
    int b = blockIdx.y;
    int i4 = blockIdx.x * blockDim.x + threadIdx.x;
    float4 pv = reinterpret_cast<const float4*>(ph)[i4];
    int m = (i4 * 4) & (Dn - 1);
    float4 xv = *reinterpret_cast<const float4*>(x + (size_t)b * Dn + m);
    float vv[4] = {cosf(pv.x) * xv.x, cosf(pv.y) * xv.y,
                   cosf(pv.z) * xv.z, cosf(pv.w) * xv.w};
    __half h[4], l[4];
    #pragma unroll
    for (int q = 0; q < 4; ++q) split_f32h(vv[q], h[q], l[q]);
    size_t o2 = ((size_t)b << 19) + (size_t)i4 * 2;
    reinterpret_cast<__half2*>(g_Ahf)[o2]     = __half2(h[0], h[1]);
    reinterpret_cast<__half2*>(g_Ahf)[o2 + 1] = __half2(h[2], h[3]);
    reinterpret_cast<__half2*>(g_Alf)[o2]     = __half2(l[0], l[1]);
    reinterpret_cast<__half2*>(g_Alf)[o2 + 1] = __half2(l[2], l[3]);
}

__global__ void transpose_split_E_kernel(const float* __restrict__ in) {
    __shared__ float tile[32][33];
    int x = blockIdx.x * 32 + threadIdx.x;
    int y = blockIdx.y * 32 + threadIdx.y;
    #pragma unroll
    for (int j = 0; j < 32; j += 8)
        tile[threadIdx.y + j][threadIdx.x] = in[(y + j) * Dn + x];
    __syncthreads();
    x = blockIdx.y * 32 + threadIdx.x;
    y = blockIdx.x * 32 + threadIdx.y;
    #pragma unroll
    for (int j = 0; j < 32; j += 8) {
        float v = tile[threadIdx.x][threadIdx.y + j];
        bf16 h, l; split_f32(v, h, l);
        g_ETh[(y + j) * Dn + x] = h;
        g_ETl[(y + j) * Dn + x] = l;
    }
}

// ---------------------------------------------------------------------------
// mma.sync m16n8k16 (row.col): bf16 (chains) and fp16 (final)
// ---------------------------------------------------------------------------
__device__ __forceinline__ void mma_bf16(float* c, const uint32_t* a, const uint32_t* b) {
    asm volatile(
        "mma.sync.aligned.m16n8k16.row.col.f32.bf16.bf16.f32 "
        "{%0,%1,%2,%3}, {%4,%5,%6,%7}, {%8,%9}, {%0,%1,%2,%3};"
        : "+f"(c[0]), "+f"(c[1]), "+f"(c[2]), "+f"(c[3])
        : "r"(a[0]), "r"(a[1]), "r"(a[2]), "r"(a[3]), "r"(b[0]), "r"(b[1]));
}
__device__ __forceinline__ void mma_f16(float* c, const uint32_t* a, const uint32_t* b) {
    asm volatile(
        "mma.sync.aligned.m16n8k16.row.col.f32.f16.f16.f32 "
        "{%0,%1,%2,%3}, {%4,%5,%6,%7}, {%8,%9}, {%0,%1,%2,%3};"
        : "+f"(c[0]), "+f"(c[1]), "+f"(c[2]), "+f"(c[3])
        : "r"(a[0]), "r"(a[1]), "r"(a[2]), "r"(a[3]), "r"(b[0]), "r"(b[1]));
}

// ---------------------------------------------------------------------------
// Chain split GEMM body (proven): C[i,n] = sum_k A[i,k]*B[n,k]
// WMODE 1: write C as bf16 hi/lo; WMODE 2: write C as single fp16.
// ---------------------------------------------------------------------------
template <int WMODE>
__device__ __forceinline__ void gemm_split_body(
        const bf16* __restrict__ Ah, const bf16* __restrict__ Al,
        const bf16* __restrict__ Bh, const bf16* __restrict__ Bl,
        bf16* __restrict__ Ch, bf16* __restrict__ Cl, __half* __restrict__ C16) {
    constexpr int BM = 128, BK = 32;
    constexpr int PA = BK + 8;
    constexpr int MT = 4, NT = 4;

    __shared__ bf16 sAh[BM * PA];
    __shared__ bf16 sAl[BM * PA];
    __shared__ bf16 sBh[BM * PA];
    __shared__ bf16 sBl[BM * PA];

    const int i0 = blockIdx.y * BM;
    const int n0 = blockIdx.x * BM;

    const int tid  = threadIdx.x;
    const int w    = tid >> 5;
    const int lane = tid & 31;
    const int wm   = w >> 2;
    const int wn   = w & 3;
    const int gid  = lane >> 2;
    const int tig  = lane & 3;

    float acc[MT][NT][4];
    #pragma unroll
    for (int mt = 0; mt < MT; ++mt)
        #pragma unroll
        for (int nt = 0; nt < NT; ++nt)
            #pragma unroll
            for (int q = 0; q < 4; ++q) acc[mt][nt][q] = 0.f;

    for (int k0 = 0; k0 < Dn; k0 += BK) {
        #pragma unroll
        for (int l = 0; l < 2; ++l) {
            int idx = tid + l * 256;
            int row = idx >> 2, c8 = (idx & 3) * 8;
            size_t goA = (size_t)(i0 + row) * Dn + k0 + c8;
            size_t goB = (size_t)(n0 + row) * Dn + k0 + c8;
            int so = row * PA + c8;
            *reinterpret_cast<uint4*>(&sAh[so]) = *reinterpret_cast<const uint4*>(Ah + goA);
            *reinterpret_cast<uint4*>(&sAl[so]) = *reinterpret_cast<const uint4*>(Al + goA);
            *reinterpret_cast<uint4*>(&sBh[so]) = *reinterpret_cast<const uint4*>(Bh + goB);
            *reinterpret_cast<uint4*>(&sBl[so]) = *reinterpret_cast<const uint4*>(Bl + goB);
        }
        __syncthreads();

        #pragma unroll
        for (int ks = 0; ks < BK; ks += 16) {
            uint32_t bh[NT][2], bl[NT][2];
            #pragma unroll
            for (int nt = 0; nt < NT; ++nt) {
                int bn = wn * 32 + nt * 8 + gid;
                int o = bn * PA + ks + tig * 2;
                bh[nt][0] = *reinterpret_cast<const uint32_t*>(&sBh[o]);
                bh[nt][1] = *reinterpret_cast<const uint32_t*>(&sBh[o + 8]);
                bl[nt][0] = *reinterpret_cast<const uint32_t*>(&sBl[o]);
                bl[nt][1] = *reinterpret_cast<const uint32_t*>(&sBl[o + 8]);
            }
            #pragma unroll
            for (int mt = 0; mt < MT; ++mt) {
                int ar = wm * 64 + mt * 16 + gid;
                int o0 = ar * PA + ks + tig * 2, o1 = o0 + 8 * PA;
                uint32_t ah[4], al[4];
                ah[0] = *reinterpret_cast<const uint32_t*>(&sAh[o0]);
                ah[1] = *reinterpret_cast<const uint32_t*>(&sAh[o1]);
                ah[2] = *reinterpret_cast<const uint32_t*>(&sAh[o0 + 8]);
                ah[3] = *reinterpret_cast<const uint32_t*>(&sAh[o1 + 8]);
                al[0] = *reinterpret_cast<const uint32_t*>(&sAl[o0]);
                al[1] = *reinterpret_cast<const uint32_t*>(&sAl[o1]);
                al[2] = *reinterpret_cast<const uint32_t*>(&sAl[o0 + 8]);
                al[3] = *reinterpret_cast<const uint32_t*>(&sAl[o1 + 8]);
                #pragma unroll
                for (int nt = 0; nt < NT; ++nt) {
                    mma_bf16(acc[mt][nt], ah, bh[nt]);
                    mma_bf16(acc[mt][nt], ah, bl[nt]);
                    mma_bf16(acc[mt][nt], al, bh[nt]);
                }
            }
        }
        __syncthreads();
    }

    #pragma unroll
    for (int mt = 0; mt < MT; ++mt) {
        int row = i0 + wm * 64 + mt * 16 + gid;
        #pragma unroll
        for (int nt = 0; nt < NT; ++nt) {
            int col = n0 + wn * 32 + nt * 8 + tig * 2;
            if (WMODE == 1) {
                bf16 h0, l0, h1, l1;
                split_f32(acc[mt][nt][0], h0, l0);
                split_f32(acc[mt][nt][1], h1, l1);
                *reinterpret_cast<bf162*>(Ch + (size_t)row * Dn + col) = bf162(h0, h1);
                *reinterpret_cast<bf162*>(Cl + (size_t)row * Dn + col) = bf162(l0, l1);
                split_f32(acc[mt][nt][2], h0, l0);
                split_f32(acc[mt][nt][3], h1, l1);
                *reinterpret_cast<bf162*>(Ch + (size_t)(row + 8) * Dn + col) = bf162(h0, h1);
                *reinterpret_cast<bf162*>(Cl + (size_t)(row + 8) * Dn + col) = bf162(l0, l1);
            } else {
                __half2 v0(__float2half_rn(acc[mt][nt][0]), __float2half_rn(acc[mt][nt][1]));
                __half2 v1(__float2half_rn(acc[mt][nt][2]), __float2half_rn(acc[mt][nt][3]));
                *reinterpret_cast<__half2*>(C16 + (size_t)row * Dn + col) = v0;
                *reinterpret_cast<__half2*>(C16 + (size_t)(row + 8) * Dn + col) = v1;
            }
        }
    }
}

__global__ void __launch_bounds__(256, 1) gemm_M_kernel() {
    gemm_split_body<1>(g_QWh, g_QWl, g_ETh, g_ETl, g_Mh, g_Ml, nullptr);
}
// G^T directly as fp16: C[k,m] = sum_j Wsum[k,j]*M[m,j]
__global__ void __launch_bounds__(256, 1) gemm_GT_kernel() {
    gemm_split_body<2>(g_Wh, g_Wl, g_Mh, g_Ml, nullptr, nullptr, g_GTf);
}

// ---------------------------------------------------------------------------
// Final GEMM, fp16 2-pass asymmetric split (A split hi/lo, GT single fp16):
// out[b,i,k] = sum_m A[b,i,m] * GT[k,m] + mb[k]
// BK=16, 2 stages, 3 smem arrays, 2 CTAs/SM. Mainloop: 2 MMA per (mt,nt).
// ---------------------------------------------------------------------------
__global__ void __launch_bounds__(256, 2)
gemm_final_kernel(float* __restrict__ out) {
    constexpr int BK = 16;
    constexpr int PA = BK + 8;
    constexpr int PAB = PA * 2;
    constexpr int MT = 4, NT = 4;
    constexpr int NK = Dn / BK;

    __shared__ __half sAh[2][128 * PA];
    __shared__ __half sAl[2][128 * PA];
    __shared__ __half sBf[2][128 * PA];

    const int b  = blockIdx.z;
    const int i0 = blockIdx.y * 128;
    const int n0 = blockIdx.x * 128;
    const __half* __restrict__ Ahb = g_Ahf + ((size_t)b << 20);
    const __half* __restrict__ Alb = g_Alf + ((size_t)b << 20);

    const int tid  = threadIdx.x;
    const int w    = tid >> 5;
    const int lane = tid & 31;
    const int wm   = w >> 2;
    const int wn   = w & 3;
    const int gid  = lane >> 2;
    const int tig  = lane & 3;

    const int crow = tid >> 1;
    const int cc8  = (tid & 1) * 8;
    const int cso  = crow * PA + cc8;
    uint32_t cAh[2], cAl[2], cBf[2];
    cAh[0] = smem_u32(&sAh[0][cso]); cAh[1] = smem_u32(&sAh[1][cso]);
    cAl[0] = smem_u32(&sAl[0][cso]); cAl[1] = smem_u32(&sAl[1][cso]);
    cBf[0] = smem_u32(&sBf[0][cso]); cBf[1] = smem_u32(&sBf[1][cso]);
    const size_t gA = (size_t)(i0 + crow) * Dn + cc8;
    const size_t gB = (size_t)(n0 + crow) * Dn + cc8;

    const uint32_t aOff = (uint32_t)((wm * 64 + (lane & 15)) * PAB + (lane >> 4) * 16);
    const uint32_t bOff = (uint32_t)((wn * 32 + (lane & 7) + ((lane >> 4) << 3)) * PAB
                                     + ((lane >> 3) & 1) * 16);
    uint32_t aHa[2], aLa[2], bFa[2];
    aHa[0] = smem_u32(&sAh[0][0]) + aOff; aHa[1] = smem_u32(&sAh[1][0]) + aOff;
    aLa[0] = smem_u32(&sAl[0][0]) + aOff; aLa[1] = smem_u32(&sAl[1][0]) + aOff;
    bFa[0] = smem_u32(&sBf[0][0]) + bOff; bFa[1] = smem_u32(&sBf[1][0]) + bOff;

    float acc[MT][NT][4];
    #pragma unroll
    for (int mt = 0; mt < MT; ++mt)
        #pragma unroll
        for (int nt = 0; nt < NT; ++nt)
            #pragma unroll
            for (int q = 0; q < 4; ++q) acc[mt][nt][q] = 0.f;

    cp_async16(cAh[0], Ahb + gA);
    cp_async16(cAl[0], Alb + gA);
    cp_async16(cBf[0], g_GTf + gB);
    cp_commit();

    for (int kt = 0; kt < NK; ++kt) {
        int st = kt & 1;
        if (kt + 1 < NK) {
            int ko = (kt + 1) * BK;
            int ns = st ^ 1;
            cp_async16(cAh[ns], Ahb + gA + ko);
            cp_async16(cAl[ns], Alb + gA + ko);
            cp_async16(cBf[ns], g_GTf + gB + ko);
        }
        cp_commit();
        cp_wait1();
        __syncthreads();

        // B fragments: 2 ldmatrix.x4 (single fp16 array; covers nt pairs)
        uint32_t bf[NT][2];
        #pragma unroll
        for (int j = 0; j < 2; ++j) {
            uint32_t r0, r1, r2, r3;
            ldsm_x4(r0, r1, r2, r3, bFa[st] + j * 16 * PAB);
            bf[2 * j][0] = r0; bf[2 * j][1] = r1;
            bf[2 * j + 1][0] = r2; bf[2 * j + 1][1] = r3;
        }
        #pragma unroll
        for (int mt = 0; mt < MT; ++mt) {
            uint32_t ah[4], al[4];
            ldsm_x4(ah[0], ah[1], ah[2], ah[3], aHa[st] + mt * 16 * PAB);
            ldsm_x4(al[0], al[1], al[2], al[3], aLa[st] + mt * 16 * PAB);
            #pragma unroll
            for (int nt = 0; nt < NT; ++nt) {
                mma_f16(acc[mt][nt], ah, bf[nt]);
                mma_f16(acc[mt][nt], al, bf[nt]);
            }
        }
        __syncthreads();
    }

    float* __restrict__ outb = out + (size_t)b * Dn * Dn;
    #pragma unroll
    for (int mt = 0; mt < MT; ++mt) {
        int row = i0 + wm * 64 + mt * 16 + gid;
        #pragma unroll
        for (int nt = 0; nt < NT; ++nt) {
            int col = n0 + wn * 32 + nt * 8 + tig * 2;
            float2 mbv = *reinterpret_cast<const float2*>(&g_mb[col]);
            float2 v0 = {acc[mt][nt][0] + mbv.x, acc[mt][nt][1] + mbv.y};
            float2 v1 = {acc[mt][nt][2] + mbv.x, acc[mt][nt][3] + mbv.y};
            *reinterpret_cast<float2*>(outb + (size_t)row * Dn + col) = v0;
            *reinterpret_cast<float2*>(outb + (size_t)(row + 8) * Dn + col) = v1;
        }
    }
}

// ---------------------------------------------------------------------------
// kernel_launch — dual-stream fork/join (exact R11 resource budget:
// 1 stream + 3 events, proven to pass the allocation guard).
// ---------------------------------------------------------------------------
extern "C" void kernel_launch(void* const* d_in, const int* in_sizes, int n_in,
                              void* d_out, int out_size) {
    const float* x  = (const float*)d_in[0];
    const float* qw = (const float*)d_in[1];
    const float* ph = (const float*)d_in[2];
    const float* em = (const float*)d_in[3];
    const float* gw = (const float*)d_in[4];
    const float* gb = (const float*)d_in[5];
    float* out = (float*)d_out;

    static cudaStream_t s2 = nullptr;
    static cudaEvent_t eFork = nullptr, eM = nullptr, eJoin = nullptr;
    static bool init_tried = false;
    if (!init_tried) {
        init_tried = true;
        if (cudaStreamCreateWithFlags(&s2, cudaStreamNonBlocking) != cudaSuccess) s2 = nullptr;
        if (s2) {
            cudaEventCreateWithFlags(&eFork, cudaEventDisableTiming);
            cudaEventCreateWithFlags(&eM,    cudaEventDisableTiming);
            cudaEventCreateWithFlags(&eJoin, cudaEventDisableTiming);
        }
    }

    const dim3 finGrid(Dn / 128, Dn / 128, Bn);

    if (s2) {
        // fork
        cudaEventRecord(eFork, 0);
        cudaStreamWaitEvent(s2, eFork, 0);
        // branch A (main stream): the 400MB HBM-bound reduction
        reduce_w_kernel<<<(Dn * Dn / 4) / 256, 256>>>(gw);
        // branch B (s2): small-kernel chain
        reduce_b_kernel<<<Dn / 256, 256, 0, s2>>>(gb);
        split_QW_kernel<<<(Dn * Dn / 4) / 256, 256, 0, s2>>>(qw);
        transpose_split_E_kernel<<<dim3(Dn / 32, Dn / 32), dim3(32, 8), 0, s2>>>(em);
        gemm_M_kernel<<<dim3(Dn / 128, Dn / 128), 256, 0, s2>>>();
        cudaEventRecord(eM, s2);
        split_A_kernel<<<dim3((Dn * Dn / 4) / 256, Bn), 256, 0, s2>>>(x, ph);
        cudaEventRecord(eJoin, s2);
        // join: GT needs Wsum (branch A) + M (eM)
        cudaStreamWaitEvent(0, eM, 0);
        gemm_GT_kernel<<<dim3(Dn / 128, Dn / 128), 256>>>();
        cudaStreamWaitEvent(0, eJoin, 0);
        gemm_final_kernel<<<finGrid, 256>>>(out);
    } else {
        // fallback: single-stream, dependency-correct order
        reduce_b_kernel<<<Dn / 256, 256>>>(gb);
        split_QW_kernel<<<(Dn * Dn / 4) / 256, 256>>>(qw);
        transpose_split_E_kernel<<<dim3(Dn / 32, Dn / 32), dim3(32, 8)>>>(em);
        gemm_M_kernel<<<dim3(Dn / 128, Dn / 128), 256>>>();
        split_A_kernel<<<dim3((Dn * Dn / 4) / 256, Bn), 256>>>(x, ph);
        reduce_w_kernel<<<(Dn * Dn / 4) / 256, 256>>>(gw);
        gemm_GT_kernel<<<dim3(Dn / 128, Dn / 128), 256>>>();
        gemm_final_kernel<<<finGrid, 256>>>(out);
    }
}

// round 15
// speedup vs baseline: 1.7053x; 1.2301x over previous
#include <cuda_runtime.h>
#include <cuda_bf16.h>
#include <cuda_fp16.h>
#include <cstdint>

#define Dn 1024
#define Bn 16
#define Rn 100

typedef __nv_bfloat16 bf16;
typedef __nv_bfloat162 bf162;

// Scratch (device globals; no allocations allowed).
// ONLY referenced from device code (Round-6 lesson).
__device__ float g_mb[Dn];
__device__ bf16 g_QWh[Dn * Dn], g_QWl[Dn * Dn];
__device__ bf16 g_ETh[Dn * Dn], g_ETl[Dn * Dn];
__device__ bf16 g_Wh[Dn * Dn],  g_Wl[Dn * Dn];
__device__ bf16 g_Mh[Dn * Dn],  g_Ml[Dn * Dn];
__device__ __half g_GTf[Dn * Dn];            // GT single fp16 [k,m]
__device__ __half g_Af[Bn * Dn * Dn];        // A single fp16 [b,i,m]

__device__ __forceinline__ void split_f32(float v, bf16& h, bf16& l) {
    h = __float2bfloat16_rn(v);
    l = __float2bfloat16_rn(v - __bfloat162float(h));
}

__device__ __forceinline__ void cp_async16(uint32_t dst_smem, const void* src) {
    asm volatile("cp.async.cg.shared.global [%0], [%1], 16;" :: "r"(dst_smem), "l"(src));
}
__device__ __forceinline__ void cp_commit() { asm volatile("cp.async.commit_group;"); }
__device__ __forceinline__ void cp_wait1() { asm volatile("cp.async.wait_group 1;"); }

__device__ __forceinline__ uint32_t smem_u32(const void* p) {
    uint32_t a;
    asm("{ .reg .u64 t; cvta.to.shared.u64 t, %1; cvt.u32.u64 %0, t; }" : "=r"(a) : "l"(p));
    return a;
}

__device__ __forceinline__ void ldsm_x4(uint32_t& r0, uint32_t& r1, uint32_t& r2, uint32_t& r3,
                                        uint32_t addr) {
    asm volatile("ldmatrix.sync.aligned.m8n8.x4.shared.b16 {%0,%1,%2,%3}, [%4];"
                 : "=r"(r0), "=r"(r1), "=r"(r2), "=r"(r3) : "r"(addr));
}

// ---------------------------------------------------------------------------
// Prework kernels (proven)
// ---------------------------------------------------------------------------
__global__ void reduce_w_kernel(const float* __restrict__ gw) {
    int i4 = blockIdx.x * blockDim.x + threadIdx.x;
    const float4* p = reinterpret_cast<const float4*>(gw);
    float ax = 0.f, ay = 0.f, az = 0.f, aw = 0.f;
    #pragma unroll 4
    for (int r = 0; r < Rn; ++r) {
        float4 v = p[(size_t)r * (Dn * Dn / 4) + i4];
        ax += v.x; ay += v.y; az += v.z; aw += v.w;
    }
    const float inv = 1.0f / (float)Rn;
    float vv[4] = {ax * inv, ay * inv, az * inv, aw * inv};
    bf16 h[4], l[4];
    #pragma unroll
    for (int q = 0; q < 4; ++q) split_f32(vv[q], h[q], l[q]);
    reinterpret_cast<bf162*>(g_Wh)[i4 * 2]     = bf162(h[0], h[1]);
    reinterpret_cast<bf162*>(g_Wh)[i4 * 2 + 1] = bf162(h[2], h[3]);
    reinterpret_cast<bf162*>(g_Wl)[i4 * 2]     = bf162(l[0], l[1]);
    reinterpret_cast<bf162*>(g_Wl)[i4 * 2 + 1] = bf162(l[2], l[3]);
}

__global__ void reduce_b_kernel(const float* __restrict__ gb) {
    int k = blockIdx.x * blockDim.x + threadIdx.x;
    float acc = 0.f;
    #pragma unroll 4
    for (int r = 0; r < Rn; ++r) acc += gb[r * Dn + k];
    g_mb[k] = acc / (float)Rn;
}

__global__ void split_QW_kernel(const float* __restrict__ qw) {
    int i4 = blockIdx.x * blockDim.x + threadIdx.x;
    float4 v = reinterpret_cast<const float4*>(qw)[i4];
    float vv[4] = {v.x, v.y, v.z, v.w};
    bf16 h[4], l[4];
    #pragma unroll
    for (int q = 0; q < 4; ++q) split_f32(vv[q], h[q], l[q]);
    reinterpret_cast<bf162*>(g_QWh)[i4 * 2]     = bf162(h[0], h[1]);
    reinterpret_cast<bf162*>(g_QWh)[i4 * 2 + 1] = bf162(h[2], h[3]);
    reinterpret_cast<bf162*>(g_QWl)[i4 * 2]     = bf162(l[0], l[1]);
    reinterpret_cast<bf162*>(g_QWl)[i4 * 2 + 1] = bf162(l[2], l[3]);
}

// A[b,i,m] = cos(ph[i,m]) * x[b,m] -> single fp16 (cos fused)
__global__ void split_A_kernel(const float* __restrict__ x, const float* __restrict__ ph) {
    int b = blockIdx.y;
    int i4 = blockIdx.x * blockDim.x + threadIdx.x;
    float4 pv = reinterpret_cast<const float4*>(ph)[i4];
    int m = (i4 * 4) & (Dn - 1);
    float4 xv = *reinterpret_cast<const float4*>(x + (size_t)b * Dn + m);
    __half2 v01(__float2half_rn(cosf(pv.x) * xv.x), __float2half_rn(cosf(pv.y) * xv.y));
    __half2 v23(__float2half_rn(cosf(pv.z) * xv.z), __float2half_rn(cosf(pv.w) * xv.w));
    size_t o2 = ((size_t)b << 19) + (size_t)i4 * 2;
    reinterpret_cast<__half2*>(g_Af)[o2]     = v01;
    reinterpret_cast<__half2*>(g_Af)[o2 + 1] = v23;
}

__global__ void transpose_split_E_kernel(const float* __restrict__ in) {
    __shared__ float tile[32][33];
    int x = blockIdx.x * 32 + threadIdx.x;
    int y = blockIdx.y * 32 + threadIdx.y;
    #pragma unroll
    for (int j = 0; j < 32; j += 8)
        tile[threadIdx.y + j][threadIdx.x] = in[(y + j) * Dn + x];
    __syncthreads();
    x = blockIdx.y * 32 + threadIdx.x;
    y = blockIdx.x * 32 + threadIdx.y;
    #pragma unroll
    for (int j = 0; j < 32; j += 8) {
        float v = tile[threadIdx.x][threadIdx.y + j];
        bf16 h, l; split_f32(v, h, l);
        g_ETh[(y + j) * Dn + x] = h;
        g_ETl[(y + j) * Dn + x] = l;
    }
}

// ---------------------------------------------------------------------------
// mma.sync m16n8k16 (row.col): bf16 (chains) and fp16 (final)
// ---------------------------------------------------------------------------
__device__ __forceinline__ void mma_bf16(float* c, const uint32_t* a, const uint32_t* b) {
    asm volatile(
        "mma.sync.aligned.m16n8k16.row.col.f32.bf16.bf16.f32 "
        "{%0,%1,%2,%3}, {%4,%5,%6,%7}, {%8,%9}, {%0,%1,%2,%3};"
        : "+f"(c[0]), "+f"(c[1]), "+f"(c[2]), "+f"(c[3])
        : "r"(a[0]), "r"(a[1]), "r"(a[2]), "r"(a[3]), "r"(b[0]), "r"(b[1]));
}
__device__ __forceinline__ void mma_f16(float* c, const uint32_t* a, const uint32_t* b) {
    asm volatile(
        "mma.sync.aligned.m16n8k16.row.col.f32.f16.f16.f32 "
        "{%0,%1,%2,%3}, {%4,%5,%6,%7}, {%8,%9}, {%0,%1,%2,%3};"
        : "+f"(c[0]), "+f"(c[1]), "+f"(c[2]), "+f"(c[3])
        : "r"(a[0]), "r"(a[1]), "r"(a[2]), "r"(a[3]), "r"(b[0]), "r"(b[1]));
}

// ---------------------------------------------------------------------------
// Chain split GEMM body (proven): C[i,n] = sum_k A[i,k]*B[n,k]
// WMODE 1: write C as bf16 hi/lo; WMODE 2: write C as single fp16.
// ---------------------------------------------------------------------------
template <int WMODE>
__device__ __forceinline__ void gemm_split_body(
        const bf16* __restrict__ Ah, const bf16* __restrict__ Al,
        const bf16* __restrict__ Bh, const bf16* __restrict__ Bl,
        bf16* __restrict__ Ch, bf16* __restrict__ Cl, __half* __restrict__ C16) {
    constexpr int BM = 128, BK = 32;
    constexpr int PA = BK + 8;
    constexpr int MT = 4, NT = 4;

    __shared__ bf16 sAh[BM * PA];
    __shared__ bf16 sAl[BM * PA];
    __shared__ bf16 sBh[BM * PA];
    __shared__ bf16 sBl[BM * PA];

    const int i0 = blockIdx.y * BM;
    const int n0 = blockIdx.x * BM;

    const int tid  = threadIdx.x;
    const int w    = tid >> 5;
    const int lane = tid & 31;
    const int wm   = w >> 2;
    const int wn   = w & 3;
    const int gid  = lane >> 2;
    const int tig  = lane & 3;

    float acc[MT][NT][4];
    #pragma unroll
    for (int mt = 0; mt < MT; ++mt)
        #pragma unroll
        for (int nt = 0; nt < NT; ++nt)
            #pragma unroll
            for (int q = 0; q < 4; ++q) acc[mt][nt][q] = 0.f;

    for (int k0 = 0; k0 < Dn; k0 += BK) {
        #pragma unroll
        for (int l = 0; l < 2; ++l) {
            int idx = tid + l * 256;
            int row = idx >> 2, c8 = (idx & 3) * 8;
            size_t goA = (size_t)(i0 + row) * Dn + k0 + c8;
            size_t goB = (size_t)(n0 + row) * Dn + k0 + c8;
            int so = row * PA + c8;
            *reinterpret_cast<uint4*>(&sAh[so]) = *reinterpret_cast<const uint4*>(Ah + goA);
            *reinterpret_cast<uint4*>(&sAl[so]) = *reinterpret_cast<const uint4*>(Al + goA);
            *reinterpret_cast<uint4*>(&sBh[so]) = *reinterpret_cast<const uint4*>(Bh + goB);
            *reinterpret_cast<uint4*>(&sBl[so]) = *reinterpret_cast<const uint4*>(Bl + goB);
        }
        __syncthreads();

        #pragma unroll
        for (int ks = 0; ks < BK; ks += 16) {
            uint32_t bh[NT][2], bl[NT][2];
            #pragma unroll
            for (int nt = 0; nt < NT; ++nt) {
                int bn = wn * 32 + nt * 8 + gid;
                int o = bn * PA + ks + tig * 2;
                bh[nt][0] = *reinterpret_cast<const uint32_t*>(&sBh[o]);
                bh[nt][1] = *reinterpret_cast<const uint32_t*>(&sBh[o + 8]);
                bl[nt][0] = *reinterpret_cast<const uint32_t*>(&sBl[o]);
                bl[nt][1] = *reinterpret_cast<const uint32_t*>(&sBl[o + 8]);
            }
            #pragma unroll
            for (int mt = 0; mt < MT; ++mt) {
                int ar = wm * 64 + mt * 16 + gid;
                int o0 = ar * PA + ks + tig * 2, o1 = o0 + 8 * PA;
                uint32_t ah[4], al[4];
                ah[0] = *reinterpret_cast<const uint32_t*>(&sAh[o0]);
                ah[1] = *reinterpret_cast<const uint32_t*>(&sAh[o1]);
                ah[2] = *reinterpret_cast<const uint32_t*>(&sAh[o0 + 8]);
                ah[3] = *reinterpret_cast<const uint32_t*>(&sAh[o1 + 8]);
                al[0] = *reinterpret_cast<const uint32_t*>(&sAl[o0]);
                al[1] = *reinterpret_cast<const uint32_t*>(&sAl[o1]);
                al[2] = *reinterpret_cast<const uint32_t*>(&sAl[o0 + 8]);
                al[3] = *reinterpret_cast<const uint32_t*>(&sAl[o1 + 8]);
                #pragma unroll
                for (int nt = 0; nt < NT; ++nt) {
                    mma_bf16(acc[mt][nt], ah, bh[nt]);
                    mma_bf16(acc[mt][nt], ah, bl[nt]);
                    mma_bf16(acc[mt][nt], al, bh[nt]);
                }
            }
        }
        __syncthreads();
    }

    #pragma unroll
    for (int mt = 0; mt < MT; ++mt) {
        int row = i0 + wm * 64 + mt * 16 + gid;
        #pragma unroll
        for (int nt = 0; nt < NT; ++nt) {
            int col = n0 + wn * 32 + nt * 8 + tig * 2;
            if (WMODE == 1) {
                bf16 h0, l0, h1, l1;
                split_f32(acc[mt][nt][0], h0, l0);
                split_f32(acc[mt][nt][1], h1, l1);
                *reinterpret_cast<bf162*>(Ch + (size_t)row * Dn + col) = bf162(h0, h1);
                *reinterpret_cast<bf162*>(Cl + (size_t)row * Dn + col) = bf162(l0, l1);
                split_f32(acc[mt][nt][2], h0, l0);
                split_f32(acc[mt][nt][3], h1, l1);
                *reinterpret_cast<bf162*>(Ch + (size_t)(row + 8) * Dn + col) = bf162(h0, h1);
                *reinterpret_cast<bf162*>(Cl + (size_t)(row + 8) * Dn + col) = bf162(l0, l1);
            } else {
                __half2 v0(__float2half_rn(acc[mt][nt][0]), __float2half_rn(acc[mt][nt][1]));
                __half2 v1(__float2half_rn(acc[mt][nt][2]), __float2half_rn(acc[mt][nt][3]));
                *reinterpret_cast<__half2*>(C16 + (size_t)row * Dn + col) = v0;
                *reinterpret_cast<__half2*>(C16 + (size_t)(row + 8) * Dn + col) = v1;
            }
        }
    }
}

__global__ void __launch_bounds__(256, 1) gemm_M_kernel() {
    gemm_split_body<1>(g_QWh, g_QWl, g_ETh, g_ETl, g_Mh, g_Ml, nullptr);
}
// G^T directly as fp16: C[k,m] = sum_j Wsum[k,j]*M[m,j]
__global__ void __launch_bounds__(256, 1) gemm_GT_kernel() {
    gemm_split_body<2>(g_Wh, g_Wl, g_Mh, g_Ml, nullptr, nullptr, g_GTf);
}

// ---------------------------------------------------------------------------
// Final GEMM, single-pass fp16 (A fp16, GT fp16):
// out[b,i,k] = sum_m A[b,i,m] * GT[k,m] + mb[k]
// BK=16, 2 stages, 2 smem arrays, 2 CTAs/SM. Mainloop: 1 MMA per (mt,nt).
// ---------------------------------------------------------------------------
__global__ void __launch_bounds__(256, 2)
gemm_final_kernel(float* __restrict__ out) {
    constexpr int BK = 16;
    constexpr int PA = BK + 8;
    constexpr int PAB = PA * 2;
    constexpr int MT = 4, NT = 4;
    constexpr int NK = Dn / BK;

    __shared__ __half sAf[2][128 * PA];
    __shared__ __half sBf[2][128 * PA];

    const int b  = blockIdx.z;
    const int i0 = blockIdx.y * 128;
    const int n0 = blockIdx.x * 128;
    const __half* __restrict__ Ab = g_Af + ((size_t)b << 20);

    const int tid  = threadIdx.x;
    const int w    = tid >> 5;
    const int lane = tid & 31;
    const int wm   = w >> 2;
    const int wn   = w & 3;
    const int gid  = lane >> 2;
    const int tig  = lane & 3;

    const int crow = tid >> 1;
    const int cc8  = (tid & 1) * 8;
    const int cso  = crow * PA + cc8;
    uint32_t cAf[2], cBf[2];
    cAf[0] = smem_u32(&sAf[0][cso]); cAf[1] = smem_u32(&sAf[1][cso]);
    cBf[0] = smem_u32(&sBf[0][cso]); cBf[1] = smem_u32(&sBf[1][cso]);
    const size_t gA = (size_t)(i0 + crow) * Dn + cc8;
    const size_t gB = (size_t)(n0 + crow) * Dn + cc8;

    const uint32_t aOff = (uint32_t)((wm * 64 + (lane & 15)) * PAB + (lane >> 4) * 16);
    const uint32_t bOff = (uint32_t)((wn * 32 + (lane & 7) + ((lane >> 4) << 3)) * PAB
                                     + ((lane >> 3) & 1) * 16);
    uint32_t aFa[2], bFa[2];
    aFa[0] = smem_u32(&sAf[0][0]) + aOff; aFa[1] = smem_u32(&sAf[1][0]) + aOff;
    bFa[0] = smem_u32(&sBf[0][0]) + bOff; bFa[1] = smem_u32(&sBf[1][0]) + bOff;

    float acc[MT][NT][4];
    #pragma unroll
    for (int mt = 0; mt < MT; ++mt)
        #pragma unroll
        for (int nt = 0; nt < NT; ++nt)
            #pragma unroll
            for (int q = 0; q < 4; ++q) acc[mt][nt][q] = 0.f;

    cp_async16(cAf[0], Ab + gA);
    cp_async16(cBf[0], g_GTf + gB);
    cp_commit();

    for (int kt = 0; kt < NK; ++kt) {
        int st = kt & 1;
        if (kt + 1 < NK) {
            int ko = (kt + 1) * BK;
            int ns = st ^ 1;
            cp_async16(cAf[ns], Ab + gA + ko);
            cp_async16(cBf[ns], g_GTf + gB + ko);
        }
        cp_commit();
        cp_wait1();
        __syncthreads();

        // B fragments: 2 ldmatrix.x4 (covers nt pairs)
        uint32_t bf[NT][2];
        #pragma unroll
        for (int j = 0; j < 2; ++j) {
            uint32_t r0, r1, r2, r3;
            ldsm_x4(r0, r1, r2, r3, bFa[st] + j * 16 * PAB);
            bf[2 * j][0] = r0; bf[2 * j][1] = r1;
            bf[2 * j + 1][0] = r2; bf[2 * j + 1][1] = r3;
        }
        #pragma unroll
        for (int mt = 0; mt < MT; ++mt) {
            uint32_t af[4];
            ldsm_x4(af[0], af[1], af[2], af[3], aFa[st] + mt * 16 * PAB);
            #pragma unroll
            for (int nt = 0; nt < NT; ++nt)
                mma_f16(acc[mt][nt], af, bf[nt]);
        }
        __syncthreads();
    }

    float* __restrict__ outb = out + (size_t)b * Dn * Dn;
    #pragma unroll
    for (int mt = 0; mt < MT; ++mt) {
        int row = i0 + wm * 64 + mt * 16 + gid;
        #pragma unroll
        for (int nt = 0; nt < NT; ++nt) {
            int col = n0 + wn * 32 + nt * 8 + tig * 2;
            float2 mbv = *reinterpret_cast<const float2*>(&g_mb[col]);
            float2 v0 = {acc[mt][nt][0] + mbv.x, acc[mt][nt][1] + mbv.y};
            float2 v1 = {acc[mt][nt][2] + mbv.x, acc[mt][nt][3] + mbv.y};
            *reinterpret_cast<float2*>(outb + (size_t)row * Dn + col) = v0;
            *reinterpret_cast<float2*>(outb + (size_t)(row + 8) * Dn + col) = v1;
        }
    }
}

// ---------------------------------------------------------------------------
// kernel_launch — dual-stream fork/join (proven resource budget:
// 1 stream + 3 events, passes the allocation guard).
// ---------------------------------------------------------------------------
extern "C" void kernel_launch(void* const* d_in, const int* in_sizes, int n_in,
                              void* d_out, int out_size) {
    const float* x  = (const float*)d_in[0];
    const float* qw = (const float*)d_in[1];
    const float* ph = (const float*)d_in[2];
    const float* em = (const float*)d_in[3];
    const float* gw = (const float*)d_in[4];
    const float* gb = (const float*)d_in[5];
    float* out = (float*)d_out;

    static cudaStream_t s2 = nullptr;
    static cudaEvent_t eFork = nullptr, eM = nullptr, eJoin = nullptr;
    static bool init_tried = false;
    if (!init_tried) {
        init_tried = true;
        if (cudaStreamCreateWithFlags(&s2, cudaStreamNonBlocking) != cudaSuccess) s2 = nullptr;
        if (s2) {
            cudaEventCreateWithFlags(&eFork, cudaEventDisableTiming);
            cudaEventCreateWithFlags(&eM,    cudaEventDisableTiming);
            cudaEventCreateWithFlags(&eJoin, cudaEventDisableTiming);
        }
    }

    const dim3 finGrid(Dn / 128, Dn / 128, Bn);

    if (s2) {
        // fork
        cudaEventRecord(eFork, 0);
        cudaStreamWaitEvent(s2, eFork, 0);
        // branch A (main stream): the 400MB HBM-bound reduction
        reduce_w_kernel<<<(Dn * Dn / 4) / 256, 256>>>(gw);
        // branch B (s2): small-kernel chain
        reduce_b_kernel<<<Dn / 256, 256, 0, s2>>>(gb);
        split_QW_kernel<<<(Dn * Dn / 4) / 256, 256, 0, s2>>>(qw);
        transpose_split_E_kernel<<<dim3(Dn / 32, Dn / 32), dim3(32, 8), 0, s2>>>(em);
        gemm_M_kernel<<<dim3(Dn / 128, Dn / 128), 256, 0, s2>>>();
        cudaEventRecord(eM, s2);
        split_A_kernel<<<dim3((Dn * Dn / 4) / 256, Bn), 256, 0, s2>>>(x, ph);
        cudaEventRecord(eJoin, s2);
        // join: GT needs Wsum (branch A) + M (eM)
        cudaStreamWaitEvent(0, eM, 0);
        gemm_GT_kernel<<<dim3(Dn / 128, Dn / 128), 256>>>();
        cudaStreamWaitEvent(0, eJoin, 0);
        gemm_final_kernel<<<finGrid, 256>>>(out);
    } else {
        // fallback: single-stream, dependency-correct order
        reduce_b_kernel<<<Dn / 256, 256>>>(gb);
        split_QW_kernel<<<(Dn * Dn / 4) / 256, 256>>>(qw);
        transpose_split_E_kernel<<<dim3(Dn / 32, Dn / 32), dim3(32, 8)>>>(em);
        gemm_M_kernel<<<dim3(Dn / 128, Dn / 128), 256>>>();
        split_A_kernel<<<dim3((Dn * Dn / 4) / 256, Bn), 256>>>(x, ph);
        reduce_w_kernel<<<(Dn * Dn / 4) / 256, 256>>>(gw);
        gemm_GT_kernel<<<dim3(Dn / 128, Dn / 128), 256>>>();
        gemm_final_kernel<<<finGrid, 256>>>(out);
    }
}

// round 16
// speedup vs baseline: 1.8437x; 1.0811x over previous
#include <cuda_runtime.h>
#include <cuda_bf16.h>
#include <cuda_fp16.h>
#include <cstdint>

#define Dn 1024
#define Bn 16
#define Rn 100

typedef __nv_bfloat16 bf16;
typedef __nv_bfloat162 bf162;

// Scratch (device globals; no allocations allowed).
// ONLY referenced from device code (Round-6 lesson).
__device__ float g_mb[Dn];
__device__ bf16 g_QWh[Dn * Dn], g_QWl[Dn * Dn];
__device__ bf16 g_ETh[Dn * Dn], g_ETl[Dn * Dn];
__device__ bf16 g_Wh[Dn * Dn],  g_Wl[Dn * Dn];
__device__ bf16 g_Mh[Dn * Dn],  g_Ml[Dn * Dn];
__device__ __half g_GTf[Dn * Dn];            // GT single fp16 [k,m]
__device__ __half g_Af[Bn * Dn * Dn];        // A single fp16 [b,i,m]

__device__ __forceinline__ void split_f32(float v, bf16& h, bf16& l) {
    h = __float2bfloat16_rn(v);
    l = __float2bfloat16_rn(v - __bfloat162float(h));
}

__device__ __forceinline__ void cp_async16(uint32_t dst_smem, const void* src) {
    asm volatile("cp.async.cg.shared.global [%0], [%1], 16;" :: "r"(dst_smem), "l"(src));
}
__device__ __forceinline__ void cp_commit() { asm volatile("cp.async.commit_group;"); }
__device__ __forceinline__ void cp_wait1() { asm volatile("cp.async.wait_group 1;"); }

__device__ __forceinline__ uint32_t smem_u32(const void* p) {
    uint32_t a;
    asm("{ .reg .u64 t; cvta.to.shared.u64 t, %1; cvt.u32.u64 %0, t; }" : "=r"(a) : "l"(p));
    return a;
}

__device__ __forceinline__ void ldsm_x4(uint32_t& r0, uint32_t& r1, uint32_t& r2, uint32_t& r3,
                                        uint32_t addr) {
    asm volatile("ldmatrix.sync.aligned.m8n8.x4.shared.b16 {%0,%1,%2,%3}, [%4];"
                 : "=r"(r0), "=r"(r1), "=r"(r2), "=r"(r3) : "r"(addr));
}

// ---------------------------------------------------------------------------
// Prework kernels (proven)
// ---------------------------------------------------------------------------
__global__ void reduce_w_kernel(const float* __restrict__ gw) {
    int i4 = blockIdx.x * blockDim.x + threadIdx.x;
    const float4* p = reinterpret_cast<const float4*>(gw);
    float ax = 0.f, ay = 0.f, az = 0.f, aw = 0.f;
    #pragma unroll 4
    for (int r = 0; r < Rn; ++r) {
        float4 v = p[(size_t)r * (Dn * Dn / 4) + i4];
        ax += v.x; ay += v.y; az += v.z; aw += v.w;
    }
    const float inv = 1.0f / (float)Rn;
    float vv[4] = {ax * inv, ay * inv, az * inv, aw * inv};
    bf16 h[4], l[4];
    #pragma unroll
    for (int q = 0; q < 4; ++q) split_f32(vv[q], h[q], l[q]);
    reinterpret_cast<bf162*>(g_Wh)[i4 * 2]     = bf162(h[0], h[1]);
    reinterpret_cast<bf162*>(g_Wh)[i4 * 2 + 1] = bf162(h[2], h[3]);
    reinterpret_cast<bf162*>(g_Wl)[i4 * 2]     = bf162(l[0], l[1]);
    reinterpret_cast<bf162*>(g_Wl)[i4 * 2 + 1] = bf162(l[2], l[3]);
}

__global__ void reduce_b_kernel(const float* __restrict__ gb) {
    int k = blockIdx.x * blockDim.x + threadIdx.x;
    float acc = 0.f;
    #pragma unroll 4
    for (int r = 0; r < Rn; ++r) acc += gb[r * Dn + k];
    g_mb[k] = acc / (float)Rn;
}

__global__ void split_QW_kernel(const float* __restrict__ qw) {
    int i4 = blockIdx.x * blockDim.x + threadIdx.x;
    float4 v = reinterpret_cast<const float4*>(qw)[i4];
    float vv[4] = {v.x, v.y, v.z, v.w};
    bf16 h[4], l[4];
    #pragma unroll
    for (int q = 0; q < 4; ++q) split_f32(vv[q], h[q], l[q]);
    reinterpret_cast<bf162*>(g_QWh)[i4 * 2]     = bf162(h[0], h[1]);
    reinterpret_cast<bf162*>(g_QWh)[i4 * 2 + 1] = bf162(h[2], h[3]);
    reinterpret_cast<bf162*>(g_QWl)[i4 * 2]     = bf162(l[0], l[1]);
    reinterpret_cast<bf162*>(g_QWl)[i4 * 2 + 1] = bf162(l[2], l[3]);
}

// A[b,i,m] = cos(ph[i,m]) * x[b,m] -> single fp16 (cos fused)
__global__ void split_A_kernel(const float* __restrict__ x, const float* __restrict__ ph) {
    int b = blockIdx.y;
    int i4 = blockIdx.x * blockDim.x + threadIdx.x;
    float4 pv = reinterpret_cast<const float4*>(ph)[i4];
    int m = (i4 * 4) & (Dn - 1);
    float4 xv = *reinterpret_cast<const float4*>(x + (size_t)b * Dn + m);
    __half2 v01(__float2half_rn(cosf(pv.x) * xv.x), __float2half_rn(cosf(pv.y) * xv.y));
    __half2 v23(__float2half_rn(cosf(pv.z) * xv.z), __float2half_rn(cosf(pv.w) * xv.w));
    size_t o2 = ((size_t)b << 19) + (size_t)i4 * 2;
    reinterpret_cast<__half2*>(g_Af)[o2]     = v01;
    reinterpret_cast<__half2*>(g_Af)[o2 + 1] = v23;
}

__global__ void transpose_split_E_kernel(const float* __restrict__ in) {
    __shared__ float tile[32][33];
    int x = blockIdx.x * 32 + threadIdx.x;
    int y = blockIdx.y * 32 + threadIdx.y;
    #pragma unroll
    for (int j = 0; j < 32; j += 8)
        tile[threadIdx.y + j][threadIdx.x] = in[(y + j) * Dn + x];
    __syncthreads();
    x = blockIdx.y * 32 + threadIdx.x;
    y = blockIdx.x * 32 + threadIdx.y;
    #pragma unroll
    for (int j = 0; j < 32; j += 8) {
        float v = tile[threadIdx.x][threadIdx.y + j];
        bf16 h, l; split_f32(v, h, l);
        g_ETh[(y + j) * Dn + x] = h;
        g_ETl[(y + j) * Dn + x] = l;
    }
}

// ---------------------------------------------------------------------------
// mma.sync m16n8k16 (row.col): bf16 (chains) and fp16 (final)
// ---------------------------------------------------------------------------
__device__ __forceinline__ void mma_bf16(float* c, const uint32_t* a, const uint32_t* b) {
    asm volatile(
        "mma.sync.aligned.m16n8k16.row.col.f32.bf16.bf16.f32 "
        "{%0,%1,%2,%3}, {%4,%5,%6,%7}, {%8,%9}, {%0,%1,%2,%3};"
        : "+f"(c[0]), "+f"(c[1]), "+f"(c[2]), "+f"(c[3])
        : "r"(a[0]), "r"(a[1]), "r"(a[2]), "r"(a[3]), "r"(b[0]), "r"(b[1]));
}
__device__ __forceinline__ void mma_f16(float* c, const uint32_t* a, const uint32_t* b) {
    asm volatile(
        "mma.sync.aligned.m16n8k16.row.col.f32.f16.f16.f32 "
        "{%0,%1,%2,%3}, {%4,%5,%6,%7}, {%8,%9}, {%0,%1,%2,%3};"
        : "+f"(c[0]), "+f"(c[1]), "+f"(c[2]), "+f"(c[3])
        : "r"(a[0]), "r"(a[1]), "r"(a[2]), "r"(a[3]), "r"(b[0]), "r"(b[1]));
}

// ---------------------------------------------------------------------------
// Chain split GEMM body (proven): C[i,n] = sum_k A[i,k]*B[n,k]
// WMODE 1: write C as bf16 hi/lo; WMODE 2: write C as single fp16.
// ---------------------------------------------------------------------------
template <int WMODE>
__device__ __forceinline__ void gemm_split_body(
        const bf16* __restrict__ Ah, const bf16* __restrict__ Al,
        const bf16* __restrict__ Bh, const bf16* __restrict__ Bl,
        bf16* __restrict__ Ch, bf16* __restrict__ Cl, __half* __restrict__ C16) {
    constexpr int BM = 128, BK = 32;
    constexpr int PA = BK + 8;
    constexpr int MT = 4, NT = 4;

    __shared__ bf16 sAh[BM * PA];
    __shared__ bf16 sAl[BM * PA];
    __shared__ bf16 sBh[BM * PA];
    __shared__ bf16 sBl[BM * PA];

    const int i0 = blockIdx.y * BM;
    const int n0 = blockIdx.x * BM;

    const int tid  = threadIdx.x;
    const int w    = tid >> 5;
    const int lane = tid & 31;
    const int wm   = w >> 2;
    const int wn   = w & 3;
    const int gid  = lane >> 2;
    const int tig  = lane & 3;

    float acc[MT][NT][4];
    #pragma unroll
    for (int mt = 0; mt < MT; ++mt)
        #pragma unroll
        for (int nt = 0; nt < NT; ++nt)
            #pragma unroll
            for (int q = 0; q < 4; ++q) acc[mt][nt][q] = 0.f;

    for (int k0 = 0; k0 < Dn; k0 += BK) {
        #pragma unroll
        for (int l = 0; l < 2; ++l) {
            int idx = tid + l * 256;
            int row = idx >> 2, c8 = (idx & 3) * 8;
            size_t goA = (size_t)(i0 + row) * Dn + k0 + c8;
            size_t goB = (size_t)(n0 + row) * Dn + k0 + c8;
            int so = row * PA + c8;
            *reinterpret_cast<uint4*>(&sAh[so]) = *reinterpret_cast<const uint4*>(Ah + goA);
            *reinterpret_cast<uint4*>(&sAl[so]) = *reinterpret_cast<const uint4*>(Al + goA);
            *reinterpret_cast<uint4*>(&sBh[so]) = *reinterpret_cast<const uint4*>(Bh + goB);
            *reinterpret_cast<uint4*>(&sBl[so]) = *reinterpret_cast<const uint4*>(Bl + goB);
        }
        __syncthreads();

        #pragma unroll
        for (int ks = 0; ks < BK; ks += 16) {
            uint32_t bh[NT][2], bl[NT][2];
            #pragma unroll
            for (int nt = 0; nt < NT; ++nt) {
                int bn = wn * 32 + nt * 8 + gid;
                int o = bn * PA + ks + tig * 2;
                bh[nt][0] = *reinterpret_cast<const uint32_t*>(&sBh[o]);
                bh[nt][1] = *reinterpret_cast<const uint32_t*>(&sBh[o + 8]);
                bl[nt][0] = *reinterpret_cast<const uint32_t*>(&sBl[o]);
                bl[nt][1] = *reinterpret_cast<const uint32_t*>(&sBl[o + 8]);
            }
            #pragma unroll
            for (int mt = 0; mt < MT; ++mt) {
                int ar = wm * 64 + mt * 16 + gid;
                int o0 = ar * PA + ks + tig * 2, o1 = o0 + 8 * PA;
                uint32_t ah[4], al[4];
                ah[0] = *reinterpret_cast<const uint32_t*>(&sAh[o0]);
                ah[1] = *reinterpret_cast<const uint32_t*>(&sAh[o1]);
                ah[2] = *reinterpret_cast<const uint32_t*>(&sAh[o0 + 8]);
                ah[3] = *reinterpret_cast<const uint32_t*>(&sAh[o1 + 8]);
                al[0] = *reinterpret_cast<const uint32_t*>(&sAl[o0]);
                al[1] = *reinterpret_cast<const uint32_t*>(&sAl[o1]);
                al[2] = *reinterpret_cast<const uint32_t*>(&sAl[o0 + 8]);
                al[3] = *reinterpret_cast<const uint32_t*>(&sAl[o1 + 8]);
                #pragma unroll
                for (int nt = 0; nt < NT; ++nt) {
                    mma_bf16(acc[mt][nt], ah, bh[nt]);
                    mma_bf16(acc[mt][nt], ah, bl[nt]);
                    mma_bf16(acc[mt][nt], al, bh[nt]);
                }
            }
        }
        __syncthreads();
    }

    #pragma unroll
    for (int mt = 0; mt < MT; ++mt) {
        int row = i0 + wm * 64 + mt * 16 + gid;
        #pragma unroll
        for (int nt = 0; nt < NT; ++nt) {
            int col = n0 + wn * 32 + nt * 8 + tig * 2;
            if (WMODE == 1) {
                bf16 h0, l0, h1, l1;
                split_f32(acc[mt][nt][0], h0, l0);
                split_f32(acc[mt][nt][1], h1, l1);
                *reinterpret_cast<bf162*>(Ch + (size_t)row * Dn + col) = bf162(h0, h1);
                *reinterpret_cast<bf162*>(Cl + (size_t)row * Dn + col) = bf162(l0, l1);
                split_f32(acc[mt][nt][2], h0, l0);
                split_f32(acc[mt][nt][3], h1, l1);
                *reinterpret_cast<bf162*>(Ch + (size_t)(row + 8) * Dn + col) = bf162(h0, h1);
                *reinterpret_cast<bf162*>(Cl + (size_t)(row + 8) * Dn + col) = bf162(l0, l1);
            } else {
                __half2 v0(__float2half_rn(acc[mt][nt][0]), __float2half_rn(acc[mt][nt][1]));
                __half2 v1(__float2half_rn(acc[mt][nt][2]), __float2half_rn(acc[mt][nt][3]));
                *reinterpret_cast<__half2*>(C16 + (size_t)row * Dn + col) = v0;
                *reinterpret_cast<__half2*>(C16 + (size_t)(row + 8) * Dn + col) = v1;
            }
        }
    }
}

__global__ void __launch_bounds__(256, 1) gemm_M_kernel() {
    gemm_split_body<1>(g_QWh, g_QWl, g_ETh, g_ETl, g_Mh, g_Ml, nullptr);
}
// G^T directly as fp16: C[k,m] = sum_j Wsum[k,j]*M[m,j]
__global__ void __launch_bounds__(256, 1) gemm_GT_kernel() {
    gemm_split_body<2>(g_Wh, g_Wl, g_Mh, g_Ml, nullptr, nullptr, g_GTf);
}

// ---------------------------------------------------------------------------
// Final GEMM, single-pass fp16, BK=32 (2 k-subtiles per stage):
// out[b,i,k] = sum_m A[b,i,m] * GT[k,m] + mb[k]
// 2 stages, 2 smem arrays (40KB), 2 CTAs/SM. 32 MMA + 12 LDSM per iter.
// ---------------------------------------------------------------------------
__global__ void __launch_bounds__(256, 2)
gemm_final_kernel(float* __restrict__ out) {
    constexpr int BK = 32;
    constexpr int PA = BK + 8;       // 40 fp16 elements per row
    constexpr int PAB = PA * 2;      // 80 bytes per row
    constexpr int MT = 4, NT = 4;
    constexpr int NK = Dn / BK;      // 32

    __shared__ __half sAf[2][128 * PA];
    __shared__ __half sBf[2][128 * PA];

    const int b  = blockIdx.z;
    const int i0 = blockIdx.y * 128;
    const int n0 = blockIdx.x * 128;
    const __half* __restrict__ Ab = g_Af + ((size_t)b << 20);

    const int tid  = threadIdx.x;
    const int w    = tid >> 5;
    const int lane = tid & 31;
    const int wm   = w >> 2;
    const int wn   = w & 3;
    const int gid  = lane >> 2;
    const int tig  = lane & 3;

    // cp.async: 128 rows x 32 cols = 512 x 16B chunks per array; 2 per thread
    const int crow = tid >> 2;                 // 0..63  (first half rows) via idx mapping below
    // Use idx mapping: idx = tid + l*256, row = idx>>2, c8 = (idx&3)*8
    const size_t gAr = (size_t)i0 * Dn;
    const size_t gBr = (size_t)n0 * Dn;

    uint32_t sA0 = smem_u32(&sAf[0][0]), sA1 = smem_u32(&sAf[1][0]);
    uint32_t sB0 = smem_u32(&sBf[0][0]), sB1 = smem_u32(&sBf[1][0]);

    // ldmatrix per-lane addresses
    const uint32_t aOff = (uint32_t)((wm * 64 + (lane & 15)) * PAB + (lane >> 4) * 16);
    const uint32_t bOff = (uint32_t)((wn * 32 + (lane & 7) + ((lane >> 4) << 3)) * PAB
                                     + ((lane >> 3) & 1) * 16);

    float acc[MT][NT][4];
    #pragma unroll
    for (int mt = 0; mt < MT; ++mt)
        #pragma unroll
        for (int nt = 0; nt < NT; ++nt)
            #pragma unroll
            for (int q = 0; q < 4; ++q) acc[mt][nt][q] = 0.f;

    // prologue: stage 0 <- kt 0
    #pragma unroll
    for (int l = 0; l < 2; ++l) {
        int idx = tid + l * 256;
        int row = idx >> 2, c8 = (idx & 3) * 8;
        uint32_t so = (uint32_t)(row * PA + c8) * 2;
        cp_async16(sA0 + so, Ab + gAr + (size_t)row * Dn + c8);
        cp_async16(sB0 + so, g_GTf + gBr + (size_t)row * Dn + c8);
    }
    cp_commit();

    for (int kt = 0; kt < NK; ++kt) {
        int st = kt & 1;
        if (kt + 1 < NK) {
            int ko = (kt + 1) * BK;
            uint32_t dA = st ? sA0 : sA1;
            uint32_t dB = st ? sB0 : sB1;
            #pragma unroll
            for (int l = 0; l < 2; ++l) {
                int idx = tid + l * 256;
                int row = idx >> 2, c8 = (idx & 3) * 8;
                uint32_t so = (uint32_t)(row * PA + c8) * 2;
                cp_async16(dA + so, Ab + gAr + (size_t)row * Dn + ko + c8);
                cp_async16(dB + so, g_GTf + gBr + (size_t)row * Dn + ko + c8);
            }
        }
        cp_commit();
        cp_wait1();
        __syncthreads();

        const uint32_t aBase = (st ? sA1 : sA0) + aOff;
        const uint32_t bBase = (st ? sB1 : sB0) + bOff;

        #pragma unroll
        for (int ks = 0; ks < 2; ++ks) {
            uint32_t bf[NT][2];
            #pragma unroll
            for (int j = 0; j < 2; ++j) {
                uint32_t r0, r1, r2, r3;
                ldsm_x4(r0, r1, r2, r3, bBase + ks * 32 + j * 16 * PAB);
                bf[2 * j][0] = r0; bf[2 * j][1] = r1;
                bf[2 * j + 1][0] = r2; bf[2 * j + 1][1] = r3;
            }
            #pragma unroll
            for (int mt = 0; mt < MT; ++mt) {
                uint32_t af[4];
                ldsm_x4(af[0], af[1], af[2], af[3], aBase + ks * 32 + mt * 16 * PAB);
                #pragma unroll
                for (int nt = 0; nt < NT; ++nt)
                    mma_f16(acc[mt][nt], af, bf[nt]);
            }
        }
        __syncthreads();
    }

    float* __restrict__ outb = out + (size_t)b * Dn * Dn;
    #pragma unroll
    for (int mt = 0; mt < MT; ++mt) {
        int row = i0 + wm * 64 + mt * 16 + gid;
        #pragma unroll
        for (int nt = 0; nt < NT; ++nt) {
            int col = n0 + wn * 32 + nt * 8 + tig * 2;
            float2 mbv = *reinterpret_cast<const float2*>(&g_mb[col]);
            float2 v0 = {acc[mt][nt][0] + mbv.x, acc[mt][nt][1] + mbv.y};
            float2 v1 = {acc[mt][nt][2] + mbv.x, acc[mt][nt][3] + mbv.y};
            *reinterpret_cast<float2*>(outb + (size_t)row * Dn + col) = v0;
            *reinterpret_cast<float2*>(outb + (size_t)(row + 8) * Dn + col) = v1;
        }
    }
}

// ---------------------------------------------------------------------------
// kernel_launch — dual-stream fork/join (proven resource budget:
// 1 stream + 3 events, passes the allocation guard).
// ---------------------------------------------------------------------------
extern "C" void kernel_launch(void* const* d_in, const int* in_sizes, int n_in,
                              void* d_out, int out_size) {
    const float* x  = (const float*)d_in[0];
    const float* qw = (const float*)d_in[1];
    const float* ph = (const float*)d_in[2];
    const float* em = (const float*)d_in[3];
    const float* gw = (const float*)d_in[4];
    const float* gb = (const float*)d_in[5];
    float* out = (float*)d_out;

    static cudaStream_t s2 = nullptr;
    static cudaEvent_t eFork = nullptr, eM = nullptr, eJoin = nullptr;
    static bool init_tried = false;
    if (!init_tried) {
        init_tried = true;
        if (cudaStreamCreateWithFlags(&s2, cudaStreamNonBlocking) != cudaSuccess) s2 = nullptr;
        if (s2) {
            cudaEventCreateWithFlags(&eFork, cudaEventDisableTiming);
            cudaEventCreateWithFlags(&eM,    cudaEventDisableTiming);
            cudaEventCreateWithFlags(&eJoin, cudaEventDisableTiming);
        }
    }

    const dim3 finGrid(Dn / 128, Dn / 128, Bn);

    if (s2) {
        // fork
        cudaEventRecord(eFork, 0);
        cudaStreamWaitEvent(s2, eFork, 0);
        // branch A (main stream): the 400MB HBM-bound reduction
        reduce_w_kernel<<<(Dn * Dn / 4) / 256, 256>>>(gw);
        // branch B (s2): small-kernel chain
        reduce_b_kernel<<<Dn / 256, 256, 0, s2>>>(gb);
        split_QW_kernel<<<(Dn * Dn / 4) / 256, 256, 0, s2>>>(qw);
        transpose_split_E_kernel<<<dim3(Dn / 32, Dn / 32), dim3(32, 8), 0, s2>>>(em);
        gemm_M_kernel<<<dim3(Dn / 128, Dn / 128), 256, 0, s2>>>();
        cudaEventRecord(eM, s2);
        split_A_kernel<<<dim3((Dn * Dn / 4) / 256, Bn), 256, 0, s2>>>(x, ph);
        cudaEventRecord(eJoin, s2);
        // join: GT needs Wsum (branch A) + M (eM)
        cudaStreamWaitEvent(0, eM, 0);
        gemm_GT_kernel<<<dim3(Dn / 128, Dn / 128), 256>>>();
        cudaStreamWaitEvent(0, eJoin, 0);
        gemm_final_kernel<<<finGrid, 256>>>(out);
    } else {
        // fallback: single-stream, dependency-correct order
        reduce_b_kernel<<<Dn / 256, 256>>>(gb);
        split_QW_kernel<<<(Dn * Dn / 4) / 256, 256>>>(qw);
        transpose_split_E_kernel<<<dim3(Dn / 32, Dn / 32), dim3(32, 8)>>>(em);
        gemm_M_kernel<<<dim3(Dn / 128, Dn / 128), 256>>>();
        split_A_kernel<<<dim3((Dn * Dn / 4) / 256, Bn), 256>>>(x, ph);
        reduce_w_kernel<<<(Dn * Dn / 4) / 256, 256>>>(gw);
        gemm_GT_kernel<<<dim3(Dn / 128, Dn / 128), 256>>>();
        gemm_final_kernel<<<finGrid, 256>>>(out);
    }
}

// round 17
// speedup vs baseline: 1.9030x; 1.0321x over previous
#include <cuda_runtime.h>
#include <cuda_bf16.h>
#include <cuda_fp16.h>
#include <cstdint>

#define Dn 1024
#define Bn 16
#define Rn 100

typedef __nv_bfloat16 bf16;
typedef __nv_bfloat162 bf162;

// Scratch (device globals; no allocations allowed).
// ONLY referenced from device code (Round-6 lesson).
__device__ float g_mb[Dn];
__device__ bf16 g_QWh[Dn * Dn], g_QWl[Dn * Dn];
__device__ bf16 g_ETh[Dn * Dn], g_ETl[Dn * Dn];
__device__ bf16 g_Wh[Dn * Dn],  g_Wl[Dn * Dn];
__device__ bf16 g_Mh[Dn * Dn],  g_Ml[Dn * Dn];
__device__ __half g_GTf[Dn * Dn];            // GT single fp16 [k,m]
__device__ __half g_Af[Bn * Dn * Dn];        // A single fp16 [b,i,m]

__device__ __forceinline__ void split_f32(float v, bf16& h, bf16& l) {
    h = __float2bfloat16_rn(v);
    l = __float2bfloat16_rn(v - __bfloat162float(h));
}

__device__ __forceinline__ void cp_async16(uint32_t dst_smem, const void* src) {
    asm volatile("cp.async.cg.shared.global [%0], [%1], 16;" :: "r"(dst_smem), "l"(src));
}
__device__ __forceinline__ void cp_commit() { asm volatile("cp.async.commit_group;"); }
__device__ __forceinline__ void cp_wait1() { asm volatile("cp.async.wait_group 1;"); }

__device__ __forceinline__ uint32_t smem_u32(const void* p) {
    uint32_t a;
    asm("{ .reg .u64 t; cvta.to.shared.u64 t, %1; cvt.u32.u64 %0, t; }" : "=r"(a) : "l"(p));
    return a;
}

__device__ __forceinline__ void ldsm_x4(uint32_t& r0, uint32_t& r1, uint32_t& r2, uint32_t& r3,
                                        uint32_t addr) {
    asm volatile("ldmatrix.sync.aligned.m8n8.x4.shared.b16 {%0,%1,%2,%3}, [%4];"
                 : "=r"(r0), "=r"(r1), "=r"(r2), "=r"(r3) : "r"(addr));
}

// ---------------------------------------------------------------------------
// Prework kernels (proven)
// ---------------------------------------------------------------------------
__global__ void reduce_w_kernel(const float* __restrict__ gw) {
    int i4 = blockIdx.x * blockDim.x + threadIdx.x;
    const float4* p = reinterpret_cast<const float4*>(gw);
    float ax = 0.f, ay = 0.f, az = 0.f, aw = 0.f;
    #pragma unroll 4
    for (int r = 0; r < Rn; ++r) {
        float4 v = p[(size_t)r * (Dn * Dn / 4) + i4];
        ax += v.x; ay += v.y; az += v.z; aw += v.w;
    }
    const float inv = 1.0f / (float)Rn;
    float vv[4] = {ax * inv, ay * inv, az * inv, aw * inv};
    bf16 h[4], l[4];
    #pragma unroll
    for (int q = 0; q < 4; ++q) split_f32(vv[q], h[q], l[q]);
    reinterpret_cast<bf162*>(g_Wh)[i4 * 2]     = bf162(h[0], h[1]);
    reinterpret_cast<bf162*>(g_Wh)[i4 * 2 + 1] = bf162(h[2], h[3]);
    reinterpret_cast<bf162*>(g_Wl)[i4 * 2]     = bf162(l[0], l[1]);
    reinterpret_cast<bf162*>(g_Wl)[i4 * 2 + 1] = bf162(l[2], l[3]);
}

__global__ void reduce_b_kernel(const float* __restrict__ gb) {
    int k = blockIdx.x * blockDim.x + threadIdx.x;
    float acc = 0.f;
    #pragma unroll 4
    for (int r = 0; r < Rn; ++r) acc += gb[r * Dn + k];
    g_mb[k] = acc / (float)Rn;
}

__global__ void split_QW_kernel(const float* __restrict__ qw) {
    int i4 = blockIdx.x * blockDim.x + threadIdx.x;
    float4 v = reinterpret_cast<const float4*>(qw)[i4];
    float vv[4] = {v.x, v.y, v.z, v.w};
    bf16 h[4], l[4];
    #pragma unroll
    for (int q = 0; q < 4; ++q) split_f32(vv[q], h[q], l[q]);
    reinterpret_cast<bf162*>(g_QWh)[i4 * 2]     = bf162(h[0], h[1]);
    reinterpret_cast<bf162*>(g_QWh)[i4 * 2 + 1] = bf162(h[2], h[3]);
    reinterpret_cast<bf162*>(g_QWl)[i4 * 2]     = bf162(l[0], l[1]);
    reinterpret_cast<bf162*>(g_QWl)[i4 * 2 + 1] = bf162(l[2], l[3]);
}

// A[b,i,m] = cos(ph[i,m]) * x[b,m] -> single fp16 (cos fused)
__global__ void split_A_kernel(const float* __restrict__ x, const float* __restrict__ ph) {
    int b = blockIdx.y;
    int i4 = blockIdx.x * blockDim.x + threadIdx.x;
    float4 pv = reinterpret_cast<const float4*>(ph)[i4];
    int m = (i4 * 4) & (Dn - 1);
    float4 xv = *reinterpret_cast<const float4*>(x + (size_t)b * Dn + m);
    __half2 v01(__float2half_rn(cosf(pv.x) * xv.x), __float2half_rn(cosf(pv.y) * xv.y));
    __half2 v23(__float2half_rn(cosf(pv.z) * xv.z), __float2half_rn(cosf(pv.w) * xv.w));
    size_t o2 = ((size_t)b << 19) + (size_t)i4 * 2;
    reinterpret_cast<__half2*>(g_Af)[o2]     = v01;
    reinterpret_cast<__half2*>(g_Af)[o2 + 1] = v23;
}

__global__ void transpose_split_E_kernel(const float* __restrict__ in) {
    __shared__ float tile[32][33];
    int x = blockIdx.x * 32 + threadIdx.x;
    int y = blockIdx.y * 32 + threadIdx.y;
    #pragma unroll
    for (int j = 0; j < 32; j += 8)
        tile[threadIdx.y + j][threadIdx.x] = in[(y + j) * Dn + x];
    __syncthreads();
    x = blockIdx.y * 32 + threadIdx.x;
    y = blockIdx.x * 32 + threadIdx.y;
    #pragma unroll
    for (int j = 0; j < 32; j += 8) {
        float v = tile[threadIdx.x][threadIdx.y + j];
        bf16 h, l; split_f32(v, h, l);
        g_ETh[(y + j) * Dn + x] = h;
        g_ETl[(y + j) * Dn + x] = l;
    }
}

// ---------------------------------------------------------------------------
// mma.sync m16n8k16 (row.col): bf16 (chains) and fp16 (final)
// ---------------------------------------------------------------------------
__device__ __forceinline__ void mma_bf16(float* c, const uint32_t* a, const uint32_t* b) {
    asm volatile(
        "mma.sync.aligned.m16n8k16.row.col.f32.bf16.bf16.f32 "
        "{%0,%1,%2,%3}, {%4,%5,%6,%7}, {%8,%9}, {%0,%1,%2,%3};"
        : "+f"(c[0]), "+f"(c[1]), "+f"(c[2]), "+f"(c[3])
        : "r"(a[0]), "r"(a[1]), "r"(a[2]), "r"(a[3]), "r"(b[0]), "r"(b[1]));
}
__device__ __forceinline__ void mma_f16(float* c, const uint32_t* a, const uint32_t* b) {
    asm volatile(
        "mma.sync.aligned.m16n8k16.row.col.f32.f16.f16.f32 "
        "{%0,%1,%2,%3}, {%4,%5,%6,%7}, {%8,%9}, {%0,%1,%2,%3};"
        : "+f"(c[0]), "+f"(c[1]), "+f"(c[2]), "+f"(c[3])
        : "r"(a[0]), "r"(a[1]), "r"(a[2]), "r"(a[3]), "r"(b[0]), "r"(b[1]));
}

// ---------------------------------------------------------------------------
// Chain split GEMM body (proven): C[i,n] = sum_k A[i,k]*B[n,k]
// WMODE 1: write C as bf16 hi/lo; WMODE 2: write C as single fp16.
// ---------------------------------------------------------------------------
template <int WMODE>
__device__ __forceinline__ void gemm_split_body(
        const bf16* __restrict__ Ah, const bf16* __restrict__ Al,
        const bf16* __restrict__ Bh, const bf16* __restrict__ Bl,
        bf16* __restrict__ Ch, bf16* __restrict__ Cl, __half* __restrict__ C16) {
    constexpr int BM = 128, BK = 32;
    constexpr int PA = BK + 8;
    constexpr int MT = 4, NT = 4;

    __shared__ bf16 sAh[BM * PA];
    __shared__ bf16 sAl[BM * PA];
    __shared__ bf16 sBh[BM * PA];
    __shared__ bf16 sBl[BM * PA];

    const int i0 = blockIdx.y * BM;
    const int n0 = blockIdx.x * BM;

    const int tid  = threadIdx.x;
    const int w    = tid >> 5;
    const int lane = tid & 31;
    const int wm   = w >> 2;
    const int wn   = w & 3;
    const int gid  = lane >> 2;
    const int tig  = lane & 3;

    float acc[MT][NT][4];
    #pragma unroll
    for (int mt = 0; mt < MT; ++mt)
        #pragma unroll
        for (int nt = 0; nt < NT; ++nt)
            #pragma unroll
            for (int q = 0; q < 4; ++q) acc[mt][nt][q] = 0.f;

    for (int k0 = 0; k0 < Dn; k0 += BK) {
        #pragma unroll
        for (int l = 0; l < 2; ++l) {
            int idx = tid + l * 256;
            int row = idx >> 2, c8 = (idx & 3) * 8;
            size_t goA = (size_t)(i0 + row) * Dn + k0 + c8;
            size_t goB = (size_t)(n0 + row) * Dn + k0 + c8;
            int so = row * PA + c8;
            *reinterpret_cast<uint4*>(&sAh[so]) = *reinterpret_cast<const uint4*>(Ah + goA);
            *reinterpret_cast<uint4*>(&sAl[so]) = *reinterpret_cast<const uint4*>(Al + goA);
            *reinterpret_cast<uint4*>(&sBh[so]) = *reinterpret_cast<const uint4*>(Bh + goB);
            *reinterpret_cast<uint4*>(&sBl[so]) = *reinterpret_cast<const uint4*>(Bl + goB);
        }
        __syncthreads();

        #pragma unroll
        for (int ks = 0; ks < BK; ks += 16) {
            uint32_t bh[NT][2], bl[NT][2];
            #pragma unroll
            for (int nt = 0; nt < NT; ++nt) {
                int bn = wn * 32 + nt * 8 + gid;
                int o = bn * PA + ks + tig * 2;
                bh[nt][0] = *reinterpret_cast<const uint32_t*>(&sBh[o]);
                bh[nt][1] = *reinterpret_cast<const uint32_t*>(&sBh[o + 8]);
                bl[nt][0] = *reinterpret_cast<const uint32_t*>(&sBl[o]);
                bl[nt][1] = *reinterpret_cast<const uint32_t*>(&sBl[o + 8]);
            }
            #pragma unroll
            for (int mt = 0; mt < MT; ++mt) {
                int ar = wm * 64 + mt * 16 + gid;
                int o0 = ar * PA + ks + tig * 2, o1 = o0 + 8 * PA;
                uint32_t ah[4], al[4];
                ah[0] = *reinterpret_cast<const uint32_t*>(&sAh[o0]);
                ah[1] = *reinterpret_cast<const uint32_t*>(&sAh[o1]);
                ah[2] = *reinterpret_cast<const uint32_t*>(&sAh[o0 + 8]);
                ah[3] = *reinterpret_cast<const uint32_t*>(&sAh[o1 + 8]);
                al[0] = *reinterpret_cast<const uint32_t*>(&sAl[o0]);
                al[1] = *reinterpret_cast<const uint32_t*>(&sAl[o1]);
                al[2] = *reinterpret_cast<const uint32_t*>(&sAl[o0 + 8]);
                al[3] = *reinterpret_cast<const uint32_t*>(&sAl[o1 + 8]);
                #pragma unroll
                for (int nt = 0; nt < NT; ++nt) {
                    mma_bf16(acc[mt][nt], ah, bh[nt]);
                    mma_bf16(acc[mt][nt], ah, bl[nt]);
                    mma_bf16(acc[mt][nt], al, bh[nt]);
                }
            }
        }
        __syncthreads();
    }

    #pragma unroll
    for (int mt = 0; mt < MT; ++mt) {
        int row = i0 + wm * 64 + mt * 16 + gid;
        #pragma unroll
        for (int nt = 0; nt < NT; ++nt) {
            int col = n0 + wn * 32 + nt * 8 + tig * 2;
            if (WMODE == 1) {
                bf16 h0, l0, h1, l1;
                split_f32(acc[mt][nt][0], h0, l0);
                split_f32(acc[mt][nt][1], h1, l1);
                *reinterpret_cast<bf162*>(Ch + (size_t)row * Dn + col) = bf162(h0, h1);
                *reinterpret_cast<bf162*>(Cl + (size_t)row * Dn + col) = bf162(l0, l1);
                split_f32(acc[mt][nt][2], h0, l0);
                split_f32(acc[mt][nt][3], h1, l1);
                *reinterpret_cast<bf162*>(Ch + (size_t)(row + 8) * Dn + col) = bf162(h0, h1);
                *reinterpret_cast<bf162*>(Cl + (size_t)(row + 8) * Dn + col) = bf162(l0, l1);
            } else {
                __half2 v0(__float2half_rn(acc[mt][nt][0]), __float2half_rn(acc[mt][nt][1]));
                __half2 v1(__float2half_rn(acc[mt][nt][2]), __float2half_rn(acc[mt][nt][3]));
                *reinterpret_cast<__half2*>(C16 + (size_t)row * Dn + col) = v0;
                *reinterpret_cast<__half2*>(C16 + (size_t)(row + 8) * Dn + col) = v1;
            }
        }
    }
}

__global__ void __launch_bounds__(256, 1) gemm_M_kernel() {
    gemm_split_body<1>(g_QWh, g_QWl, g_ETh, g_ETl, g_Mh, g_Ml, nullptr);
}
// G^T directly as fp16: C[k,m] = sum_j Wsum[k,j]*M[m,j]
__global__ void __launch_bounds__(256, 1) gemm_GT_kernel() {
    gemm_split_body<2>(g_Wh, g_Wl, g_Mh, g_Ml, nullptr, nullptr, g_GTf);
}

// ---------------------------------------------------------------------------
// Final GEMM, single-pass fp16, BK=64, dynamic smem (73728B, 2 CTAs/SM):
// out[b,i,k] = sum_m A[b,i,m] * GT[k,m] + mb[k]
// 2 stages x 2 arrays x 128 rows x 72 fp16 (144B pitch). NK=16 iterations;
// per iter: 64 MMA + 24 LDSM per warp, 8 cp.async per thread, 2 syncs.
// ---------------------------------------------------------------------------
static constexpr int FIN_ARR   = 128 * 72 * 2;               // 18432 B per array
static constexpr int FIN_SMEM  = 4 * FIN_ARR;                // 73728 B total

__global__ void __launch_bounds__(256, 2)
gemm_final_kernel(float* __restrict__ out) {
    constexpr int BK = 64;
    constexpr int PA = BK + 8;       // 72 fp16 per row
    constexpr int PAB = PA * 2;      // 144 bytes per row
    constexpr int MT = 4, NT = 4;
    constexpr int NK = Dn / BK;      // 16

    extern __shared__ char dynsm[];
    const uint32_t sb = smem_u32(dynsm);
    // layout: A0 | A1 | B0 | B1
    const uint32_t sA0 = sb;
    const uint32_t sA1 = sb + FIN_ARR;
    const uint32_t sB0 = sb + 2 * FIN_ARR;
    const uint32_t sB1 = sb + 3 * FIN_ARR;

    const int b  = blockIdx.z;
    const int i0 = blockIdx.y * 128;
    const int n0 = blockIdx.x * 128;
    const __half* __restrict__ Ab = g_Af + ((size_t)b << 20);

    const int tid  = threadIdx.x;
    const int w    = tid >> 5;
    const int lane = tid & 31;
    const int wm   = w >> 2;
    const int wn   = w & 3;
    const int gid  = lane >> 2;
    const int tig  = lane & 3;

    const size_t gAr = (size_t)i0 * Dn;
    const size_t gBr = (size_t)n0 * Dn;

    // ldmatrix per-lane offsets (within an array)
    const uint32_t aOff = (uint32_t)((wm * 64 + (lane & 15)) * PAB + (lane >> 4) * 16);
    const uint32_t bOff = (uint32_t)((wn * 32 + (lane & 7) + ((lane >> 4) << 3)) * PAB
                                     + ((lane >> 3) & 1) * 16);

    float acc[MT][NT][4];
    #pragma unroll
    for (int mt = 0; mt < MT; ++mt)
        #pragma unroll
        for (int nt = 0; nt < NT; ++nt)
            #pragma unroll
            for (int q = 0; q < 4; ++q) acc[mt][nt][q] = 0.f;

    // prologue: stage 0 <- kt 0.  128 rows x 8 chunks(16B) = 1024 per array; 4/thread.
    #pragma unroll
    for (int l = 0; l < 4; ++l) {
        int idx = tid + l * 256;
        int row = idx >> 3, ce = (idx & 7) * 8;     // element offset in row
        uint32_t so = (uint32_t)(row * PA + ce) * 2;
        cp_async16(sA0 + so, Ab + gAr + (size_t)row * Dn + ce);
        cp_async16(sB0 + so, g_GTf + gBr + (size_t)row * Dn + ce);
    }
    cp_commit();

    for (int kt = 0; kt < NK; ++kt) {
        int st = kt & 1;
        if (kt + 1 < NK) {
            int ko = (kt + 1) * BK;
            uint32_t dA = st ? sA0 : sA1;
            uint32_t dB = st ? sB0 : sB1;
            #pragma unroll
            for (int l = 0; l < 4; ++l) {
                int idx = tid + l * 256;
                int row = idx >> 3, ce = (idx & 7) * 8;
                uint32_t so = (uint32_t)(row * PA + ce) * 2;
                cp_async16(dA + so, Ab + gAr + (size_t)row * Dn + ko + ce);
                cp_async16(dB + so, g_GTf + gBr + (size_t)row * Dn + ko + ce);
            }
        }
        cp_commit();
        cp_wait1();
        __syncthreads();

        const uint32_t aBase = (st ? sA1 : sA0) + aOff;
        const uint32_t bBase = (st ? sB1 : sB0) + bOff;

        #pragma unroll
        for (int ks = 0; ks < 4; ++ks) {          // 4 k-subtiles of 16
            uint32_t bf[NT][2];
            #pragma unroll
            for (int j = 0; j < 2; ++j) {
                uint32_t r0, r1, r2, r3;
                ldsm_x4(r0, r1, r2, r3, bBase + ks * 32 + j * 16 * PAB);
                bf[2 * j][0] = r0; bf[2 * j][1] = r1;
                bf[2 * j + 1][0] = r2; bf[2 * j + 1][1] = r3;
            }
            #pragma unroll
            for (int mt = 0; mt < MT; ++mt) {
                uint32_t af[4];
                ldsm_x4(af[0], af[1], af[2], af[3], aBase + ks * 32 + mt * 16 * PAB);
                #pragma unroll
                for (int nt = 0; nt < NT; ++nt)
                    mma_f16(acc[mt][nt], af, bf[nt]);
            }
        }
        __syncthreads();
    }

    float* __restrict__ outb = out + (size_t)b * Dn * Dn;
    #pragma unroll
    for (int mt = 0; mt < MT; ++mt) {
        int row = i0 + wm * 64 + mt * 16 + gid;
        #pragma unroll
        for (int nt = 0; nt < NT; ++nt) {
            int col = n0 + wn * 32 + nt * 8 + tig * 2;
            float2 mbv = *reinterpret_cast<const float2*>(&g_mb[col]);
            float2 v0 = {acc[mt][nt][0] + mbv.x, acc[mt][nt][1] + mbv.y};
            float2 v1 = {acc[mt][nt][2] + mbv.x, acc[mt][nt][3] + mbv.y};
            *reinterpret_cast<float2*>(outb + (size_t)row * Dn + col) = v0;
            *reinterpret_cast<float2*>(outb + (size_t)(row + 8) * Dn + col) = v1;
        }
    }
}

// ---------------------------------------------------------------------------
// kernel_launch — dual-stream fork/join (proven resource budget:
// 1 stream + 3 events, passes the allocation guard).
// ---------------------------------------------------------------------------
extern "C" void kernel_launch(void* const* d_in, const int* in_sizes, int n_in,
                              void* d_out, int out_size) {
    const float* x  = (const float*)d_in[0];
    const float* qw = (const float*)d_in[1];
    const float* ph = (const float*)d_in[2];
    const float* em = (const float*)d_in[3];
    const float* gw = (const float*)d_in[4];
    const float* gb = (const float*)d_in[5];
    float* out = (float*)d_out;

    static cudaStream_t s2 = nullptr;
    static cudaEvent_t eFork = nullptr, eM = nullptr, eJoin = nullptr;
    static bool init_tried = false;
    if (!init_tried) {
        init_tried = true;
        cudaFuncSetAttribute(gemm_final_kernel,
                             cudaFuncAttributeMaxDynamicSharedMemorySize, FIN_SMEM);
        if (cudaStreamCreateWithFlags(&s2, cudaStreamNonBlocking) != cudaSuccess) s2 = nullptr;
        if (s2) {
            cudaEventCreateWithFlags(&eFork, cudaEventDisableTiming);
            cudaEventCreateWithFlags(&eM,    cudaEventDisableTiming);
            cudaEventCreateWithFlags(&eJoin, cudaEventDisableTiming);
        }
    }

    const dim3 finGrid(Dn / 128, Dn / 128, Bn);

    if (s2) {
        // fork
        cudaEventRecord(eFork, 0);
        cudaStreamWaitEvent(s2, eFork, 0);
        // branch A (main stream): the 400MB HBM-bound reduction
        reduce_w_kernel<<<(Dn * Dn / 4) / 256, 256>>>(gw);
        // branch B (s2): small-kernel chain
        reduce_b_kernel<<<Dn / 256, 256, 0, s2>>>(gb);
        split_QW_kernel<<<(Dn * Dn / 4) / 256, 256, 0, s2>>>(qw);
        transpose_split_E_kernel<<<dim3(Dn / 32, Dn / 32), dim3(32, 8), 0, s2>>>(em);
        gemm_M_kernel<<<dim3(Dn / 128, Dn / 128), 256, 0, s2>>>();
        cudaEventRecord(eM, s2);
        split_A_kernel<<<dim3((Dn * Dn / 4) / 256, Bn), 256, 0, s2>>>(x, ph);
        cudaEventRecord(eJoin, s2);
        // join: GT needs Wsum (branch A) + M (eM)
        cudaStreamWaitEvent(0, eM, 0);
        gemm_GT_kernel<<<dim3(Dn / 128, Dn / 128), 256>>>();
        cudaStreamWaitEvent(0, eJoin, 0);
        gemm_final_kernel<<<finGrid, 256, FIN_SMEM>>>(out);
    } else {
        // fallback: single-stream, dependency-correct order
        reduce_b_kernel<<<Dn / 256, 256>>>(gb);
        split_QW_kernel<<<(Dn * Dn / 4) / 256, 256>>>(qw);
        transpose_split_E_kernel<<<dim3(Dn / 32, Dn / 32), dim3(32, 8)>>>(em);
        gemm_M_kernel<<<dim3(Dn / 128, Dn / 128), 256>>>();
        split_A_kernel<<<dim3((Dn * Dn / 4) / 256, Bn), 256>>>(x, ph);
        reduce_w_kernel<<<(Dn * Dn / 4) / 256, 256>>>(gw);
        gemm_GT_kernel<<<dim3(Dn / 128, Dn / 128), 256>>>();
        gemm_final_kernel<<<finGrid, 256, FIN_SMEM>>>(out);
    }
}